// round 12
// baseline (speedup 1.0000x reference)
#include <cuda_runtime.h>
#include <math.h>

#define PI_F 3.14159265358979323846f

// Precomputed circuit data (setup_kernel -> qc_kernel)
// Odd-parity columns pre-rotated by (-i) so the matvec is a uniform f32x2 FMA.
__device__ float2 g_Uq[16][16];   // [col j][row i]
__device__ float2 g_Uv[16][16];
__device__ float  g_kx[4];        // <X_w> of the fixed k-register state

// ---------- helpers ----------
__device__ __forceinline__ float2 cmul(float2 a, float2 b){
    return make_float2(a.x*b.x - a.y*b.y, a.x*b.y + a.y*b.x);
}
__device__ __forceinline__ float2 cadd(float2 a, float2 b){ return make_float2(a.x+b.x, a.y+b.y); }
__device__ __forceinline__ float2 expi(float a){ float s,c; __sincosf(a,&s,&c); return make_float2(c,s); }
__device__ __forceinline__ float2 cscale(float2 a, float s){ return make_float2(a.x*s, a.y*s); }
__device__ __forceinline__ float2 shflx(float2 v, int m){
    return make_float2(__shfl_xor_sync(0xffffffffu, v.x, m),
                       __shfl_xor_sync(0xffffffffu, v.y, m));
}
__device__ __forceinline__ float fast_tanh(float x){
    float e = __expf(2.f * x);
    return 1.f - 2.f / (e + 1.f);
}
__device__ __forceinline__ unsigned long long pk2(float x, float y){
    unsigned long long r; asm("mov.b64 %0, {%1,%2};" : "=l"(r) : "f"(x), "f"(y)); return r;
}
__device__ __forceinline__ float2 upk2(unsigned long long a){
    float2 r; asm("mov.b64 {%0,%1}, %2;" : "=f"(r.x), "=f"(r.y) : "l"(a)); return r;
}
__device__ __forceinline__ unsigned long long fma2(unsigned long long a, unsigned long long b,
                                                   unsigned long long c){
    unsigned long long d;
    asm("fma.rn.f32x2 %0, %1, %2, %3;" : "=l"(d) : "l"(a), "l"(b), "l"(c));
    return d;
}

// Scatter-reduce 4 quad-lane partials: lane l receives the full sum of var l.
// 6 shfls instead of a full 8-shfl butterfly.
__device__ __forceinline__ float scat4(float v0, float v1, float v2, float v3, int l){
    float t0 = __shfl_xor_sync(0xffffffffu, v0, 2);
    float t1 = __shfl_xor_sync(0xffffffffu, v1, 2);
    float t2 = __shfl_xor_sync(0xffffffffu, v2, 2);
    float t3 = __shfl_xor_sync(0xffffffffu, v3, 2);
    float q0, q1;
    if (l & 2){ q0 = v2 + t2; q1 = v3 + t3; }
    else      { q0 = v0 + t0; q1 = v1 + t1; }
    q0 += __shfl_xor_sync(0xffffffffu, q0, 1);
    q1 += __shfl_xor_sync(0xffffffffu, q1, 1);
    return (l & 1) ? q1 : q0;
}

// fully-unrolled 8-gate initQKV circuit on 16 amplitudes across a 16-lane group
__device__ __forceinline__ float2 sim16(const float* __restrict__ rot,
                                        const float* __restrict__ crx,
                                        int col, int lane)
{
    float2 s = (lane == col) ? make_float2(1.f, 0.f) : make_float2(0.f, 0.f);
    #pragma unroll
    for (int g = 0; g < 8; g++){
        const int pa_[8] = {0,1,2,3,0,1,2,3};
        const int pb_[8] = {1,2,3,0,3,0,1,2};
        const int ma = 8 >> pa_[g], mb = 8 >> pb_[g];

        float phi = rot[3*g], th = rot[3*g+1], om = rot[3*g+2];
        float c, sn; __sincosf(0.5f*th, &sn, &c);
        float2 u00 = cscale(expi(-0.5f*(phi+om)),  c);
        float2 u01 = cscale(expi( 0.5f*(phi-om)), -sn);
        float2 u10 = cscale(expi(-0.5f*(phi-om)),  sn);
        float2 u11 = cscale(expi( 0.5f*(phi+om)),  c);
        float2 o = shflx(s, ma);
        s = (lane & ma) ? cadd(cmul(u10, o), cmul(u11, s))
                        : cadd(cmul(u00, s), cmul(u01, o));

        float cc, ss; __sincosf(0.5f*crx[g], &ss, &cc);
        o = shflx(s, mb);
        if (lane & ma) s = make_float2(cc*s.x + ss*o.y, cc*s.y - ss*o.x);

        o = shflx(s, mb);
        if (lane & ma) s = o;
    }
    return s;
}

// 17 blocks x 32 threads: block b handles chains 2b, 2b+1.
__global__ void __launch_bounds__(32)
setup_kernel(const float* __restrict__ qr, const float* __restrict__ kr,
             const float* __restrict__ vr, const float* __restrict__ qc,
             const float* __restrict__ kc, const float* __restrict__ vc)
{
    int grp  = blockIdx.x * 2 + (threadIdx.x >> 4);   // 0..33
    int lane = threadIdx.x & 15;

    const float* rot; const float* crx; int col;
    if (grp < 16)      { rot = qr; crx = qc; col = grp;      }
    else if (grp < 32) { rot = vr; crx = vc; col = grp - 16; }
    else               { rot = kr; crx = kc; col = 0;        }

    float2 s = sim16(rot, crx, col, lane);

    if (grp < 32){
        if (__popc(col) & 1) s = make_float2(s.y, -s.x);   // pre-rotate by (-i)
        if (grp < 16) g_Uq[col][lane] = s;
        else          g_Uv[col][lane] = s;
    } else {
        #pragma unroll
        for (int w = 0; w < 4; w++){
            int m = 8 >> w;
            float2 o = shflx(s, m);
            float v = s.x*o.x + s.y*o.y;
            v += __shfl_xor_sync(0xffffffffu, v, 1);
            v += __shfl_xor_sync(0xffffffffu, v, 2);
            v += __shfl_xor_sync(0xffffffffu, v, 4);
            v += __shfl_xor_sync(0xffffffffu, v, 8);
            if (grp == 32 && lane == 0) g_kx[w] = v;
        }
    }
}

// 128 threads = 32 quads; each quad serves TWO samples (ILP-2). 64 samples/block.
// Launched with PDL: prologue up to griddepcontrol.wait overlaps setup_kernel.
__global__ void __launch_bounds__(128, 3)
qc_kernel(const float* __restrict__ x1, const float* __restrict__ pre_w,
          const float* __restrict__ pre_b,
          const float* __restrict__ ln_w, const float* __restrict__ ln_b,
          const float* __restrict__ head_w, const float* __restrict__ head_b,
          float* __restrict__ out, int B)
{
    __shared__ float4 sUq[128];   // 16x16 complex
    __shared__ float4 sUv[128];
    __shared__ float  sW[384];    // pre_w [4][96]
    __shared__ float  sKx[4];
    __shared__ float  sPB[4];
    __shared__ float  sLnW[8], sLnB[8], sHW[16], sHB[2];

    int t = threadIdx.x;

    // ---- phase 1: stage params that do NOT depend on setup_kernel ----
    for (int i = t; i < 384; i += 128) sW[i] = pre_w[i];
    if (t < 4)              sPB[t]     = pre_b[t];
    if (t >= 4 && t < 12)   sLnW[t-4]  = ln_w[t-4];
    if (t >= 12 && t < 20)  sLnB[t-12] = ln_b[t-12];
    if (t >= 20 && t < 36)  sHW[t-20]  = head_w[t-20];
    if (t >= 36 && t < 38)  sHB[t-36]  = head_b[t-36];
    __syncthreads();

    int q = t >> 2;                      // quad id 0..31
    int l = t & 3;                       // quad lane: rows 4l..4l+3
    int sA = blockIdx.x * 64 + q;
    int sB = sA + 32;
    bool okA = sA < B, okB = sB < B;
    int sAl = okA ? sA : 0;
    int sBl = okB ? sB : 0;

    const float4* sW4 = (const float4*)sW;

    // ---- x = x1[s] @ pre_w.T + pre_b, both samples (setup-independent) ----
    float a0A=0.f,a1A=0.f,a2A=0.f,a3A=0.f, a0B=0.f,a1B=0.f,a2B=0.f,a3B=0.f;
    {
        const float4* rowA = (const float4*)(x1 + (size_t)sAl * 96) + l * 6;
        const float4* rowB = (const float4*)(x1 + (size_t)sBl * 96) + l * 6;
        #pragma unroll
        for (int k = 0; k < 6; k++){
            float4 vA = rowA[k];
            float4 vB = rowB[k];
            float4 w0 = sW4[      l*6 + k];
            float4 w1 = sW4[ 24 + l*6 + k];
            float4 w2 = sW4[ 48 + l*6 + k];
            float4 w3 = sW4[ 72 + l*6 + k];
            a0A += vA.x*w0.x + vA.y*w0.y + vA.z*w0.z + vA.w*w0.w;
            a1A += vA.x*w1.x + vA.y*w1.y + vA.z*w1.z + vA.w*w1.w;
            a2A += vA.x*w2.x + vA.y*w2.y + vA.z*w2.z + vA.w*w2.w;
            a3A += vA.x*w3.x + vA.y*w3.y + vA.z*w3.z + vA.w*w3.w;
            a0B += vB.x*w0.x + vB.y*w0.y + vB.z*w0.z + vB.w*w0.w;
            a1B += vB.x*w1.x + vB.y*w1.y + vB.z*w1.z + vB.w*w1.w;
            a2B += vB.x*w2.x + vB.y*w2.y + vB.z*w2.z + vB.w*w2.w;
            a3B += vB.x*w3.x + vB.y*w3.y + vB.z*w3.z + vB.w*w3.w;
        }
        #pragma unroll
        for (int d = 1; d <= 2; d <<= 1){
            a0A += __shfl_xor_sync(0xffffffffu, a0A, d);
            a1A += __shfl_xor_sync(0xffffffffu, a1A, d);
            a2A += __shfl_xor_sync(0xffffffffu, a2A, d);
            a3A += __shfl_xor_sync(0xffffffffu, a3A, d);
            a0B += __shfl_xor_sync(0xffffffffu, a0B, d);
            a1B += __shfl_xor_sync(0xffffffffu, a1B, d);
            a2B += __shfl_xor_sync(0xffffffffu, a2B, d);
            a3B += __shfl_xor_sync(0xffffffffu, a3B, d);
        }
    }

    float hcA[4], hsA[4], hcB[4], hsB[4];
    {
        float xwA[4] = { a0A + sPB[0], a1A + sPB[1], a2A + sPB[2], a3A + sPB[3] };
        float xwB[4] = { a0B + sPB[0], a1B + sPB[1], a2B + sPB[2], a3B + sPB[3] };
        #pragma unroll
        for (int w = 0; w < 4; w++){
            __sincosf(0.5f * xwA[w], &hsA[w], &hcA[w]);
            __sincosf(0.5f * xwB[w], &hsB[w], &hcB[w]);
        }
    }

    // product-state magnitudes ((-1) of (-i)^popc folded in; (-i) itself is in U)
    float mA[16], mB[16];
    #pragma unroll
    for (int i = 0; i < 16; i++){
        float vA = ((i&8)?hsA[0]:hcA[0]) * ((i&4)?hsA[1]:hcA[1]) * ((i&2)?hsA[2]:hcA[2]) * ((i&1)?hsA[3]:hcA[3]);
        float vB = ((i&8)?hsB[0]:hcB[0]) * ((i&4)?hsB[1]:hcB[1]) * ((i&2)?hsB[2]:hcB[2]) * ((i&1)?hsB[3]:hcB[3]);
        if (__popc(i) & 2){ vA = -vA; vB = -vB; }
        mA[i] = vA; mB[i] = vB;
    }

    // ---- phase 2: wait for setup_kernel's results, then stage them ----
    asm volatile("griddepcontrol.wait;" ::: "memory");
    sUq[t] = ((const float4*)g_Uq)[t];
    sUv[t] = ((const float4*)g_Uv)[t];
    if (t < 4) sKx[t] = g_kx[t];
    __syncthreads();

    const ulonglong2* Uq64 = (const ulonglong2*)sUq;
    const ulonglong2* Uv64 = (const ulonglong2*)sUv;

    // ---- matvecs: shared U loads serve both samples ----
    unsigned long long pqA[4], pvA[4], pqB[4], pvB[4];
    #pragma unroll
    for (int r = 0; r < 4; r++){ pqA[r]=0ull; pvA[r]=0ull; pqB[r]=0ull; pvB[r]=0ull; }
    #pragma unroll
    for (int j = 0; j < 16; j++){
        unsigned long long mjA = pk2(mA[j], mA[j]);
        unsigned long long mjB = pk2(mB[j], mB[j]);
        ulonglong2 qa = Uq64[j*8 + 2*l];
        ulonglong2 qb = Uq64[j*8 + 2*l + 1];
        ulonglong2 va = Uv64[j*8 + 2*l];
        ulonglong2 vb = Uv64[j*8 + 2*l + 1];
        pqA[0] = fma2(qa.x, mjA, pqA[0]);  pqB[0] = fma2(qa.x, mjB, pqB[0]);
        pqA[1] = fma2(qa.y, mjA, pqA[1]);  pqB[1] = fma2(qa.y, mjB, pqB[1]);
        pqA[2] = fma2(qb.x, mjA, pqA[2]);  pqB[2] = fma2(qb.x, mjB, pqB[2]);
        pqA[3] = fma2(qb.y, mjA, pqA[3]);  pqB[3] = fma2(qb.y, mjB, pqB[3]);
        pvA[0] = fma2(va.x, mjA, pvA[0]);  pvB[0] = fma2(va.x, mjB, pvB[0]);
        pvA[1] = fma2(va.y, mjA, pvA[1]);  pvB[1] = fma2(va.y, mjB, pvB[1]);
        pvA[2] = fma2(vb.x, mjA, pvA[2]);  pvB[2] = fma2(vb.x, mjB, pvB[2]);
        pvA[3] = fma2(vb.y, mjA, pvA[3]);  pvB[3] = fma2(vb.y, mjB, pvB[3]);
    }
    float2 stqA[4], stvA[4], stqB[4], stvB[4];
    #pragma unroll
    for (int r = 0; r < 4; r++){
        stqA[r] = upk2(pqA[r]); stvA[r] = upk2(pvA[r]);
        stqB[r] = upk2(pqB[r]); stvB[r] = upk2(pvB[r]);
    }

    // ---- q path: RX(x) layer (symmetric pair update), both samples ----
    #pragma unroll
    for (int w = 0; w < 2; w++){
        int d = 2 >> w;   // wire0: lane^2, wire1: lane^1
        float cA = hcA[w], sA_ = hsA[w], cB = hcB[w], sB_ = hsB[w];
        #pragma unroll
        for (int r = 0; r < 4; r++){
            float2 oA = shflx(stqA[r], d);
            float2 oB = shflx(stqB[r], d);
            stqA[r] = make_float2(cA*stqA[r].x + sA_*oA.y, cA*stqA[r].y - sA_*oA.x);
            stqB[r] = make_float2(cB*stqB[r].x + sB_*oB.y, cB*stqB[r].y - sB_*oB.x);
        }
    }
    {   // wire2 (bit1): rows r <-> r^2
        float c = hcA[2], s = hsA[2];
        float2 n0 = make_float2(c*stqA[0].x + s*stqA[2].y, c*stqA[0].y - s*stqA[2].x);
        float2 n2 = make_float2(c*stqA[2].x + s*stqA[0].y, c*stqA[2].y - s*stqA[0].x);
        float2 n1 = make_float2(c*stqA[1].x + s*stqA[3].y, c*stqA[1].y - s*stqA[3].x);
        float2 n3 = make_float2(c*stqA[3].x + s*stqA[1].y, c*stqA[3].y - s*stqA[1].x);
        stqA[0]=n0; stqA[1]=n1; stqA[2]=n2; stqA[3]=n3;
        c = hcB[2]; s = hsB[2];
        n0 = make_float2(c*stqB[0].x + s*stqB[2].y, c*stqB[0].y - s*stqB[2].x);
        n2 = make_float2(c*stqB[2].x + s*stqB[0].y, c*stqB[2].y - s*stqB[0].x);
        n1 = make_float2(c*stqB[1].x + s*stqB[3].y, c*stqB[1].y - s*stqB[3].x);
        n3 = make_float2(c*stqB[3].x + s*stqB[1].y, c*stqB[3].y - s*stqB[1].x);
        stqB[0]=n0; stqB[1]=n1; stqB[2]=n2; stqB[3]=n3;
    }
    {   // wire3 (bit0): rows r <-> r^1
        float c = hcA[3], s = hsA[3];
        float2 n0 = make_float2(c*stqA[0].x + s*stqA[1].y, c*stqA[0].y - s*stqA[1].x);
        float2 n1 = make_float2(c*stqA[1].x + s*stqA[0].y, c*stqA[1].y - s*stqA[0].x);
        float2 n2 = make_float2(c*stqA[2].x + s*stqA[3].y, c*stqA[2].y - s*stqA[3].x);
        float2 n3 = make_float2(c*stqA[3].x + s*stqA[2].y, c*stqA[3].y - s*stqA[2].x);
        stqA[0]=n0; stqA[1]=n1; stqA[2]=n2; stqA[3]=n3;
        c = hcB[3]; s = hsB[3];
        n0 = make_float2(c*stqB[0].x + s*stqB[1].y, c*stqB[0].y - s*stqB[1].x);
        n1 = make_float2(c*stqB[1].x + s*stqB[0].y, c*stqB[1].y - s*stqB[0].x);
        n2 = make_float2(c*stqB[2].x + s*stqB[3].y, c*stqB[2].y - s*stqB[3].x);
        n3 = make_float2(c*stqB[3].x + s*stqB[2].y, c*stqB[3].y - s*stqB[2].x);
        stqB[0]=n0; stqB[1]=n1; stqB[2]=n2; stqB[3]=n3;
    }

    // ---- scores: scatter-reduce; lane l computes only rz_l, then broadcast ----
    float rzA[4], rzB[4];
    {
        float n0 = stqA[0].x*stqA[0].x + stqA[0].y*stqA[0].y;
        float n1 = stqA[1].x*stqA[1].x + stqA[1].y*stqA[1].y;
        float n2 = stqA[2].x*stqA[2].x + stqA[2].y*stqA[2].y;
        float n3 = stqA[3].x*stqA[3].x + stqA[3].y*stqA[3].y;
        float nsum = n0 + n1 + n2 + n3;
        float z0A = (l & 2) ? -nsum : nsum;
        float z1A = (l & 1) ? -nsum : nsum;
        float z2A = n0 + n1 - n2 - n3;
        float z3A = n0 - n1 + n2 - n3;

        n0 = stqB[0].x*stqB[0].x + stqB[0].y*stqB[0].y;
        n1 = stqB[1].x*stqB[1].x + stqB[1].y*stqB[1].y;
        n2 = stqB[2].x*stqB[2].x + stqB[2].y*stqB[2].y;
        n3 = stqB[3].x*stqB[3].x + stqB[3].y*stqB[3].y;
        nsum = n0 + n1 + n2 + n3;
        float z0B = (l & 2) ? -nsum : nsum;
        float z1B = (l & 1) ? -nsum : nsum;
        float z2B = n0 + n1 - n2 - n3;
        float z3B = n0 - n1 + n2 - n3;

        float x0A = 0.f, x1A = 0.f, x0B = 0.f, x1B = 0.f;
        #pragma unroll
        for (int r = 0; r < 4; r++){
            float2 oA = shflx(stqA[r], 2);
            float2 oB = shflx(stqB[r], 2);
            x0A += stqA[r].x*oA.x + stqA[r].y*oA.y;
            x0B += stqB[r].x*oB.x + stqB[r].y*oB.y;
        }
        #pragma unroll
        for (int r = 0; r < 4; r++){
            float2 oA = shflx(stqA[r], 1);
            float2 oB = shflx(stqB[r], 1);
            x1A += stqA[r].x*oA.x + stqA[r].y*oA.y;
            x1B += stqB[r].x*oB.x + stqB[r].y*oB.y;
        }
        float x2A = 2.f*(stqA[0].x*stqA[2].x + stqA[0].y*stqA[2].y + stqA[1].x*stqA[3].x + stqA[1].y*stqA[3].y);
        float x3A = 2.f*(stqA[0].x*stqA[1].x + stqA[0].y*stqA[1].y + stqA[2].x*stqA[3].x + stqA[2].y*stqA[3].y);
        float x2B = 2.f*(stqB[0].x*stqB[2].x + stqB[0].y*stqB[2].y + stqB[1].x*stqB[3].x + stqB[1].y*stqB[3].y);
        float x3B = 2.f*(stqB[0].x*stqB[1].x + stqB[0].y*stqB[1].y + stqB[2].x*stqB[3].x + stqB[2].y*stqB[3].y);

        // lane l gets z_l and x_l (scatter-reduce), computes rz_l, broadcasts
        float zlA = scat4(z0A, z1A, z2A, z3A, l);
        float xlA = scat4(x0A, x1A, x2A, x3A, l) * sKx[l];
        float zlB = scat4(z0B, z1B, z2B, z3B, l);
        float xlB = scat4(x0B, x1B, x2B, x3B, l) * sKx[l];

        float rzlA = fast_tanh(sqrtf(zlA*zlA + xlA*xlA)) * (0.5f * PI_F);
        float rzlB = fast_tanh(sqrtf(zlB*zlB + xlB*xlB)) * (0.5f * PI_F);
        #pragma unroll
        for (int w = 0; w < 4; w++){
            rzA[w] = __shfl_sync(0xffffffffu, rzlA, w, 4);
            rzB[w] = __shfl_sync(0xffffffffu, rzlB, w, 4);
        }
    }

    // ---- v path: RZ phases ----
    {
        float phlA = ((l & 2) ? rzA[0] : -rzA[0]) + ((l & 1) ? rzA[1] : -rzA[1]);
        float phlB = ((l & 2) ? rzB[0] : -rzB[0]) + ((l & 1) ? rzB[1] : -rzB[1]);
        #pragma unroll
        for (int r = 0; r < 4; r++){
            float phA = phlA + ((r & 2) ? rzA[2] : -rzA[2]) + ((r & 1) ? rzA[3] : -rzA[3]);
            float phB = phlB + ((r & 2) ? rzB[2] : -rzB[2]) + ((r & 1) ? rzB[3] : -rzB[3]);
            float spA, cpA, spB, cpB;
            __sincosf(phA, &spA, &cpA);
            __sincosf(phB, &spB, &cpB);
            stvA[r] = make_float2(stvA[r].x*cpA - stvA[r].y*spA, stvA[r].x*spA + stvA[r].y*cpA);
            stvB[r] = make_float2(stvB[r].x*cpB - stvB[r].y*spB, stvB[r].x*spB + stvB[r].y*cpB);
        }
    }
    // CNOT(0,1): lanes with (l&2) take partner (l^1)'s value
    #pragma unroll
    for (int r = 0; r < 4; r++){
        float2 oA = shflx(stvA[r], 1);
        float2 oB = shflx(stvB[r], 1);
        if (l & 2){ stvA[r] = oA; stvB[r] = oB; }
    }
    // CNOT(1,2): if (l&1): swap rows r <-> r^2
    if (l & 1){
        float2 tq = stvA[0]; stvA[0] = stvA[2]; stvA[2] = tq;
        tq = stvA[1]; stvA[1] = stvA[3]; stvA[3] = tq;
        tq = stvB[0]; stvB[0] = stvB[2]; stvB[2] = tq;
        tq = stvB[1]; stvB[1] = stvB[3]; stvB[3] = tq;
    }
    // CNOT(2,3): swap rows 2,3
    { float2 tq = stvA[2]; stvA[2] = stvA[3]; stvA[3] = tq;
      tq = stvB[2]; stvB[2] = stvB[3]; stvB[3] = tq; }

    // ---- final expectations: scatter-reduce straight to owning lane ----
    // lane l owns channels 2l (even set: o0,o2,o4,o6) and 2l+1 (odd set: o1,o3,o5,o7)
    float e0A, e1A, e0B, e1B;
    {
        float n0 = stvA[0].x*stvA[0].x + stvA[0].y*stvA[0].y;
        float n1 = stvA[1].x*stvA[1].x + stvA[1].y*stvA[1].y;
        float n2 = stvA[2].x*stvA[2].x + stvA[2].y*stvA[2].y;
        float n3 = stvA[3].x*stvA[3].x + stvA[3].y*stvA[3].y;
        float qs = n0 + n1 + n2 + n3;
        float o0A = (l & 2) ? -qs : qs;
        float o1A = (l & 1) ? -qs : qs;
        float o2A = n0 + n1 - n2 - n3;
        float o3A = n0 - n1 + n2 - n3;

        n0 = stvB[0].x*stvB[0].x + stvB[0].y*stvB[0].y;
        n1 = stvB[1].x*stvB[1].x + stvB[1].y*stvB[1].y;
        n2 = stvB[2].x*stvB[2].x + stvB[2].y*stvB[2].y;
        n3 = stvB[3].x*stvB[3].x + stvB[3].y*stvB[3].y;
        qs = n0 + n1 + n2 + n3;
        float o0B = (l & 2) ? -qs : qs;
        float o1B = (l & 1) ? -qs : qs;
        float o2B = n0 + n1 - n2 - n3;
        float o3B = n0 - n1 + n2 - n3;

        float o4A = 0.f, o5A = 0.f, o4B = 0.f, o5B = 0.f;
        #pragma unroll
        for (int r = 0; r < 4; r++){
            float2 oA = shflx(stvA[r], 2);
            float2 oB = shflx(stvB[r], 2);
            o4A += stvA[r].x*oA.x + stvA[r].y*oA.y;
            o4B += stvB[r].x*oB.x + stvB[r].y*oB.y;
        }
        #pragma unroll
        for (int r = 0; r < 4; r++){
            float2 oA = shflx(stvA[r], 1);
            float2 oB = shflx(stvB[r], 1);
            o5A += stvA[r].x*oA.x + stvA[r].y*oA.y;
            o5B += stvB[r].x*oB.x + stvB[r].y*oB.y;
        }
        float o6A = 2.f*(stvA[0].x*stvA[2].x + stvA[0].y*stvA[2].y + stvA[1].x*stvA[3].x + stvA[1].y*stvA[3].y);
        float o7A = 2.f*(stvA[0].x*stvA[1].x + stvA[0].y*stvA[1].y + stvA[2].x*stvA[3].x + stvA[2].y*stvA[3].y);
        float o6B = 2.f*(stvB[0].x*stvB[2].x + stvB[0].y*stvB[2].y + stvB[1].x*stvB[3].x + stvB[1].y*stvB[3].y);
        float o7B = 2.f*(stvB[0].x*stvB[1].x + stvB[0].y*stvB[1].y + stvB[2].x*stvB[3].x + stvB[2].y*stvB[3].y);

        e0A = scat4(o0A, o2A, o4A, o6A, l);   // channel 2l
        e1A = scat4(o1A, o3A, o5A, o7A, l);   // channel 2l+1
        e0B = scat4(o0B, o2B, o4B, o6B, l);
        e1B = scat4(o1B, o3B, o5B, o7B, l);
    }

    // ---- distributed LN / GELU / head: lane l handles channels 2l, 2l+1 ----
    {
        int c0 = 2*l, c1 = 2*l + 1;

        float mpA = e0A + e1A, mpB = e0B + e1B;
        mpA += __shfl_xor_sync(0xffffffffu, mpA, 1);
        mpB += __shfl_xor_sync(0xffffffffu, mpB, 1);
        mpA += __shfl_xor_sync(0xffffffffu, mpA, 2);
        mpB += __shfl_xor_sync(0xffffffffu, mpB, 2);
        float muA = mpA * 0.125f, muB = mpB * 0.125f;

        float d0A = e0A - muA, d1A = e1A - muA;
        float d0B = e0B - muB, d1B = e1B - muB;
        float vpA = d0A*d0A + d1A*d1A;
        float vpB = d0B*d0B + d1B*d1B;
        vpA += __shfl_xor_sync(0xffffffffu, vpA, 1);
        vpB += __shfl_xor_sync(0xffffffffu, vpB, 1);
        vpA += __shfl_xor_sync(0xffffffffu, vpA, 2);
        vpB += __shfl_xor_sync(0xffffffffu, vpB, 2);
        float invA = rsqrtf(vpA * 0.125f + 1e-5f);
        float invB = rsqrtf(vpB * 0.125f + 1e-5f);

        float w0 = sLnW[c0], w1 = sLnW[c1], bb0 = sLnB[c0], bb1 = sLnB[c1];
        float y0A = d0A*invA*w0 + bb0, y1A = d1A*invA*w1 + bb1;
        float y0B = d0B*invB*w0 + bb0, y1B = d1B*invB*w1 + bb1;

        const float RS2 = 0.70710678118654752f;
        float g0A = 0.5f*y0A*(1.f + erff(y0A*RS2));
        float g1A = 0.5f*y1A*(1.f + erff(y1A*RS2));
        float g0B = 0.5f*y0B*(1.f + erff(y0B*RS2));
        float g1B = 0.5f*y1B*(1.f + erff(y1B*RS2));

        float hw00 = sHW[c0], hw01 = sHW[c1], hw10 = sHW[8+c0], hw11 = sHW[8+c1];
        float r0A = g0A*hw00 + g1A*hw01;
        float r1A = g0A*hw10 + g1A*hw11;
        float r0B = g0B*hw00 + g1B*hw01;
        float r1B = g0B*hw10 + g1B*hw11;
        r0A += __shfl_xor_sync(0xffffffffu, r0A, 1);
        r1A += __shfl_xor_sync(0xffffffffu, r1A, 1);
        r0B += __shfl_xor_sync(0xffffffffu, r0B, 1);
        r1B += __shfl_xor_sync(0xffffffffu, r1B, 1);
        r0A += __shfl_xor_sync(0xffffffffu, r0A, 2);
        r1A += __shfl_xor_sync(0xffffffffu, r1A, 2);
        r0B += __shfl_xor_sync(0xffffffffu, r0B, 2);
        r1B += __shfl_xor_sync(0xffffffffu, r1B, 2);

        if (l == 0){
            if (okA) ((float2*)out)[sA] = make_float2(r0A + sHB[0], r1A + sHB[1]);
            if (okB) ((float2*)out)[sB] = make_float2(r0B + sHB[0], r1B + sHB[1]);
        }
    }
}

extern "C" void kernel_launch(void* const* d_in, const int* in_sizes, int n_in,
                              void* d_out, int out_size)
{
    const float* x1     = (const float*)d_in[0];
    const float* pre_w  = (const float*)d_in[1];
    const float* pre_b  = (const float*)d_in[2];
    const float* q_rot  = (const float*)d_in[3];
    const float* k_rot  = (const float*)d_in[4];
    const float* v_rot  = (const float*)d_in[5];
    const float* q_crx  = (const float*)d_in[6];
    const float* k_crx  = (const float*)d_in[7];
    const float* v_crx  = (const float*)d_in[8];
    const float* ln_w   = (const float*)d_in[9];
    const float* ln_b   = (const float*)d_in[10];
    const float* head_w = (const float*)d_in[11];
    const float* head_b = (const float*)d_in[12];

    int B = in_sizes[0] / 96;

    setup_kernel<<<17, 32>>>(q_rot, k_rot, v_rot, q_crx, k_crx, v_crx);

    // PDL launch: qc's prologue overlaps setup_kernel; griddepcontrol.wait
    // inside qc orders the g_U* reads after setup completion.
    cudaLaunchConfig_t cfg = {};
    cfg.gridDim  = dim3((unsigned)((B + 63) / 64), 1, 1);
    cfg.blockDim = dim3(128, 1, 1);
    cfg.dynamicSmemBytes = 0;
    cfg.stream = 0;
    cudaLaunchAttribute attrs[1];
    attrs[0].id = cudaLaunchAttributeProgrammaticStreamSerialization;
    attrs[0].val.programmaticStreamSerializationAllowed = 1;
    cfg.attrs = attrs;
    cfg.numAttrs = 1;
    cudaLaunchKernelEx(&cfg, qc_kernel, x1, pre_w, pre_b, ln_w, ln_b,
                       head_w, head_b, (float*)d_out, B);
}

// round 13
// speedup vs baseline: 1.0025x; 1.0025x over previous
#include <cuda_runtime.h>
#include <math.h>

#define PI_F 3.14159265358979323846f

// Precomputed circuit data (setup_kernel -> qc_kernel)
// Odd-parity columns pre-rotated by (-i) so the matvec is a uniform f32x2 FMA.
__device__ float2 g_Uq[16][16];   // [col j][row i]
__device__ float2 g_Uv[16][16];
__device__ float  g_kx[4];        // <X_w> of the fixed k-register state

// ---------- helpers ----------
__device__ __forceinline__ float2 cmul(float2 a, float2 b){
    return make_float2(a.x*b.x - a.y*b.y, a.x*b.y + a.y*b.x);
}
__device__ __forceinline__ float2 cadd(float2 a, float2 b){ return make_float2(a.x+b.x, a.y+b.y); }
__device__ __forceinline__ float2 expi(float a){ float s,c; __sincosf(a,&s,&c); return make_float2(c,s); }
__device__ __forceinline__ float2 cscale(float2 a, float s){ return make_float2(a.x*s, a.y*s); }
__device__ __forceinline__ float2 shflx(float2 v, int m){
    return make_float2(__shfl_xor_sync(0xffffffffu, v.x, m),
                       __shfl_xor_sync(0xffffffffu, v.y, m));
}
__device__ __forceinline__ float fast_tanh(float x){
    float e = __expf(2.f * x);
    return 1.f - 2.f / (e + 1.f);
}
__device__ __forceinline__ unsigned long long pk2(float x, float y){
    unsigned long long r; asm("mov.b64 %0, {%1,%2};" : "=l"(r) : "f"(x), "f"(y)); return r;
}
__device__ __forceinline__ float2 upk2(unsigned long long a){
    float2 r; asm("mov.b64 {%0,%1}, %2;" : "=f"(r.x), "=f"(r.y) : "l"(a)); return r;
}
__device__ __forceinline__ unsigned long long fma2(unsigned long long a, unsigned long long b,
                                                   unsigned long long c){
    unsigned long long d;
    asm("fma.rn.f32x2 %0, %1, %2, %3;" : "=l"(d) : "l"(a), "l"(b), "l"(c));
    return d;
}

// Scatter-reduce 4 quad-lane partials: lane l receives the full sum of var l.
__device__ __forceinline__ float scat4(float v0, float v1, float v2, float v3, int l){
    float t0 = __shfl_xor_sync(0xffffffffu, v0, 2);
    float t1 = __shfl_xor_sync(0xffffffffu, v1, 2);
    float t2 = __shfl_xor_sync(0xffffffffu, v2, 2);
    float t3 = __shfl_xor_sync(0xffffffffu, v3, 2);
    float q0, q1;
    if (l & 2){ q0 = v2 + t2; q1 = v3 + t3; }
    else      { q0 = v0 + t0; q1 = v1 + t1; }
    q0 += __shfl_xor_sync(0xffffffffu, q0, 1);
    q1 += __shfl_xor_sync(0xffffffffu, q1, 1);
    return (l & 1) ? q1 : q0;
}

// fully-unrolled 8-gate initQKV circuit on 16 amplitudes across a 16-lane group
__device__ __forceinline__ float2 sim16(const float* __restrict__ rot,
                                        const float* __restrict__ crx,
                                        int col, int lane)
{
    float2 s = (lane == col) ? make_float2(1.f, 0.f) : make_float2(0.f, 0.f);
    #pragma unroll
    for (int g = 0; g < 8; g++){
        const int pa_[8] = {0,1,2,3,0,1,2,3};
        const int pb_[8] = {1,2,3,0,3,0,1,2};
        const int ma = 8 >> pa_[g], mb = 8 >> pb_[g];

        float phi = rot[3*g], th = rot[3*g+1], om = rot[3*g+2];
        float c, sn; __sincosf(0.5f*th, &sn, &c);
        float2 u00 = cscale(expi(-0.5f*(phi+om)),  c);
        float2 u01 = cscale(expi( 0.5f*(phi-om)), -sn);
        float2 u10 = cscale(expi(-0.5f*(phi-om)),  sn);
        float2 u11 = cscale(expi( 0.5f*(phi+om)),  c);
        float2 o = shflx(s, ma);
        s = (lane & ma) ? cadd(cmul(u10, o), cmul(u11, s))
                        : cadd(cmul(u00, s), cmul(u01, o));

        float cc, ss; __sincosf(0.5f*crx[g], &ss, &cc);
        o = shflx(s, mb);
        if (lane & ma) s = make_float2(cc*s.x + ss*o.y, cc*s.y - ss*o.x);

        o = shflx(s, mb);
        if (lane & ma) s = o;
    }
    return s;
}

// 17 blocks x 32 threads: block b handles chains 2b, 2b+1.
__global__ void __launch_bounds__(32)
setup_kernel(const float* __restrict__ qr, const float* __restrict__ kr,
             const float* __restrict__ vr, const float* __restrict__ qc,
             const float* __restrict__ kc, const float* __restrict__ vc)
{
    int grp  = blockIdx.x * 2 + (threadIdx.x >> 4);   // 0..33
    int lane = threadIdx.x & 15;

    const float* rot; const float* crx; int col;
    if (grp < 16)      { rot = qr; crx = qc; col = grp;      }
    else if (grp < 32) { rot = vr; crx = vc; col = grp - 16; }
    else               { rot = kr; crx = kc; col = 0;        }

    float2 s = sim16(rot, crx, col, lane);

    if (grp < 32){
        if (__popc(col) & 1) s = make_float2(s.y, -s.x);   // pre-rotate by (-i)
        if (grp < 16) g_Uq[col][lane] = s;
        else          g_Uv[col][lane] = s;
    } else {
        #pragma unroll
        for (int w = 0; w < 4; w++){
            int m = 8 >> w;
            float2 o = shflx(s, m);
            float v = s.x*o.x + s.y*o.y;
            v += __shfl_xor_sync(0xffffffffu, v, 1);
            v += __shfl_xor_sync(0xffffffffu, v, 2);
            v += __shfl_xor_sync(0xffffffffu, v, 4);
            v += __shfl_xor_sync(0xffffffffu, v, 8);
            if (grp == 32 && lane == 0) g_kx[w] = v;
        }
    }
}

// 64 threads = 16 quads; each quad serves TWO samples (ILP-2). 32 samples/block.
// grid = 512 -> 3-4 blocks per SM, every SM gets 6-8 warps (vs 40 SMs at 4 warps before).
// Launched with PDL: prologue up to griddepcontrol.wait overlaps setup_kernel.
__global__ void __launch_bounds__(64, 6)
qc_kernel(const float* __restrict__ x1, const float* __restrict__ pre_w,
          const float* __restrict__ pre_b,
          const float* __restrict__ ln_w, const float* __restrict__ ln_b,
          const float* __restrict__ head_w, const float* __restrict__ head_b,
          float* __restrict__ out, int B)
{
    __shared__ float4 sUq[128];   // 16x16 complex
    __shared__ float4 sUv[128];
    __shared__ float  sW[384];    // pre_w [4][96]
    __shared__ float  sKx[4];
    __shared__ float  sPB[4];
    __shared__ float  sLnW[8], sLnB[8], sHW[16], sHB[2];

    int t = threadIdx.x;

    // ---- phase 1: stage params that do NOT depend on setup_kernel ----
    for (int i = t; i < 384; i += 64) sW[i] = pre_w[i];
    if (t < 4)              sPB[t]     = pre_b[t];
    if (t >= 4 && t < 12)   sLnW[t-4]  = ln_w[t-4];
    if (t >= 12 && t < 20)  sLnB[t-12] = ln_b[t-12];
    if (t >= 20 && t < 36)  sHW[t-20]  = head_w[t-20];
    if (t >= 36 && t < 38)  sHB[t-36]  = head_b[t-36];
    __syncthreads();

    int q = t >> 2;                      // quad id 0..15
    int l = t & 3;                       // quad lane: rows 4l..4l+3
    int sA = blockIdx.x * 32 + q;
    int sB = sA + 16;
    bool okA = sA < B, okB = sB < B;
    int sAl = okA ? sA : 0;
    int sBl = okB ? sB : 0;

    const float4* sW4 = (const float4*)sW;

    // ---- x = x1[s] @ pre_w.T + pre_b, both samples (setup-independent) ----
    float a0A=0.f,a1A=0.f,a2A=0.f,a3A=0.f, a0B=0.f,a1B=0.f,a2B=0.f,a3B=0.f;
    {
        const float4* rowA = (const float4*)(x1 + (size_t)sAl * 96) + l * 6;
        const float4* rowB = (const float4*)(x1 + (size_t)sBl * 96) + l * 6;
        #pragma unroll
        for (int k = 0; k < 6; k++){
            float4 vA = rowA[k];
            float4 vB = rowB[k];
            float4 w0 = sW4[      l*6 + k];
            float4 w1 = sW4[ 24 + l*6 + k];
            float4 w2 = sW4[ 48 + l*6 + k];
            float4 w3 = sW4[ 72 + l*6 + k];
            a0A += vA.x*w0.x + vA.y*w0.y + vA.z*w0.z + vA.w*w0.w;
            a1A += vA.x*w1.x + vA.y*w1.y + vA.z*w1.z + vA.w*w1.w;
            a2A += vA.x*w2.x + vA.y*w2.y + vA.z*w2.z + vA.w*w2.w;
            a3A += vA.x*w3.x + vA.y*w3.y + vA.z*w3.z + vA.w*w3.w;
            a0B += vB.x*w0.x + vB.y*w0.y + vB.z*w0.z + vB.w*w0.w;
            a1B += vB.x*w1.x + vB.y*w1.y + vB.z*w1.z + vB.w*w1.w;
            a2B += vB.x*w2.x + vB.y*w2.y + vB.z*w2.z + vB.w*w2.w;
            a3B += vB.x*w3.x + vB.y*w3.y + vB.z*w3.z + vB.w*w3.w;
        }
        #pragma unroll
        for (int d = 1; d <= 2; d <<= 1){
            a0A += __shfl_xor_sync(0xffffffffu, a0A, d);
            a1A += __shfl_xor_sync(0xffffffffu, a1A, d);
            a2A += __shfl_xor_sync(0xffffffffu, a2A, d);
            a3A += __shfl_xor_sync(0xffffffffu, a3A, d);
            a0B += __shfl_xor_sync(0xffffffffu, a0B, d);
            a1B += __shfl_xor_sync(0xffffffffu, a1B, d);
            a2B += __shfl_xor_sync(0xffffffffu, a2B, d);
            a3B += __shfl_xor_sync(0xffffffffu, a3B, d);
        }
    }

    float hcA[4], hsA[4], hcB[4], hsB[4];
    {
        float xwA[4] = { a0A + sPB[0], a1A + sPB[1], a2A + sPB[2], a3A + sPB[3] };
        float xwB[4] = { a0B + sPB[0], a1B + sPB[1], a2B + sPB[2], a3B + sPB[3] };
        #pragma unroll
        for (int w = 0; w < 4; w++){
            __sincosf(0.5f * xwA[w], &hsA[w], &hcA[w]);
            __sincosf(0.5f * xwB[w], &hsB[w], &hcB[w]);
        }
    }

    // product-state magnitudes ((-1) of (-i)^popc folded in; (-i) itself is in U)
    float mA[16], mB[16];
    #pragma unroll
    for (int i = 0; i < 16; i++){
        float vA = ((i&8)?hsA[0]:hcA[0]) * ((i&4)?hsA[1]:hcA[1]) * ((i&2)?hsA[2]:hcA[2]) * ((i&1)?hsA[3]:hcA[3]);
        float vB = ((i&8)?hsB[0]:hcB[0]) * ((i&4)?hsB[1]:hcB[1]) * ((i&2)?hsB[2]:hcB[2]) * ((i&1)?hsB[3]:hcB[3]);
        if (__popc(i) & 2){ vA = -vA; vB = -vB; }
        mA[i] = vA; mB[i] = vB;
    }

    // ---- phase 2: wait for setup_kernel's results, then stage them ----
    asm volatile("griddepcontrol.wait;" ::: "memory");
    sUq[t]      = ((const float4*)g_Uq)[t];
    sUq[t + 64] = ((const float4*)g_Uq)[t + 64];
    sUv[t]      = ((const float4*)g_Uv)[t];
    sUv[t + 64] = ((const float4*)g_Uv)[t + 64];
    if (t < 4) sKx[t] = g_kx[t];
    __syncthreads();

    const ulonglong2* Uq64 = (const ulonglong2*)sUq;
    const ulonglong2* Uv64 = (const ulonglong2*)sUv;

    // ---- matvecs: shared U loads serve both samples ----
    unsigned long long pqA[4], pvA[4], pqB[4], pvB[4];
    #pragma unroll
    for (int r = 0; r < 4; r++){ pqA[r]=0ull; pvA[r]=0ull; pqB[r]=0ull; pvB[r]=0ull; }
    #pragma unroll
    for (int j = 0; j < 16; j++){
        unsigned long long mjA = pk2(mA[j], mA[j]);
        unsigned long long mjB = pk2(mB[j], mB[j]);
        ulonglong2 qa = Uq64[j*8 + 2*l];
        ulonglong2 qb = Uq64[j*8 + 2*l + 1];
        ulonglong2 va = Uv64[j*8 + 2*l];
        ulonglong2 vb = Uv64[j*8 + 2*l + 1];
        pqA[0] = fma2(qa.x, mjA, pqA[0]);  pqB[0] = fma2(qa.x, mjB, pqB[0]);
        pqA[1] = fma2(qa.y, mjA, pqA[1]);  pqB[1] = fma2(qa.y, mjB, pqB[1]);
        pqA[2] = fma2(qb.x, mjA, pqA[2]);  pqB[2] = fma2(qb.x, mjB, pqB[2]);
        pqA[3] = fma2(qb.y, mjA, pqA[3]);  pqB[3] = fma2(qb.y, mjB, pqB[3]);
        pvA[0] = fma2(va.x, mjA, pvA[0]);  pvB[0] = fma2(va.x, mjB, pvB[0]);
        pvA[1] = fma2(va.y, mjA, pvA[1]);  pvB[1] = fma2(va.y, mjB, pvB[1]);
        pvA[2] = fma2(vb.x, mjA, pvA[2]);  pvB[2] = fma2(vb.x, mjB, pvB[2]);
        pvA[3] = fma2(vb.y, mjA, pvA[3]);  pvB[3] = fma2(vb.y, mjB, pvB[3]);
    }
    float2 stqA[4], stvA[4], stqB[4], stvB[4];
    #pragma unroll
    for (int r = 0; r < 4; r++){
        stqA[r] = upk2(pqA[r]); stvA[r] = upk2(pvA[r]);
        stqB[r] = upk2(pqB[r]); stvB[r] = upk2(pvB[r]);
    }

    // ---- q path: RX(x) layer (symmetric pair update), both samples ----
    #pragma unroll
    for (int w = 0; w < 2; w++){
        int d = 2 >> w;   // wire0: lane^2, wire1: lane^1
        float cA = hcA[w], sA_ = hsA[w], cB = hcB[w], sB_ = hsB[w];
        #pragma unroll
        for (int r = 0; r < 4; r++){
            float2 oA = shflx(stqA[r], d);
            float2 oB = shflx(stqB[r], d);
            stqA[r] = make_float2(cA*stqA[r].x + sA_*oA.y, cA*stqA[r].y - sA_*oA.x);
            stqB[r] = make_float2(cB*stqB[r].x + sB_*oB.y, cB*stqB[r].y - sB_*oB.x);
        }
    }
    {   // wire2 (bit1): rows r <-> r^2
        float c = hcA[2], s = hsA[2];
        float2 n0 = make_float2(c*stqA[0].x + s*stqA[2].y, c*stqA[0].y - s*stqA[2].x);
        float2 n2 = make_float2(c*stqA[2].x + s*stqA[0].y, c*stqA[2].y - s*stqA[0].x);
        float2 n1 = make_float2(c*stqA[1].x + s*stqA[3].y, c*stqA[1].y - s*stqA[3].x);
        float2 n3 = make_float2(c*stqA[3].x + s*stqA[1].y, c*stqA[3].y - s*stqA[1].x);
        stqA[0]=n0; stqA[1]=n1; stqA[2]=n2; stqA[3]=n3;
        c = hcB[2]; s = hsB[2];
        n0 = make_float2(c*stqB[0].x + s*stqB[2].y, c*stqB[0].y - s*stqB[2].x);
        n2 = make_float2(c*stqB[2].x + s*stqB[0].y, c*stqB[2].y - s*stqB[0].x);
        n1 = make_float2(c*stqB[1].x + s*stqB[3].y, c*stqB[1].y - s*stqB[3].x);
        n3 = make_float2(c*stqB[3].x + s*stqB[1].y, c*stqB[3].y - s*stqB[1].x);
        stqB[0]=n0; stqB[1]=n1; stqB[2]=n2; stqB[3]=n3;
    }
    {   // wire3 (bit0): rows r <-> r^1
        float c = hcA[3], s = hsA[3];
        float2 n0 = make_float2(c*stqA[0].x + s*stqA[1].y, c*stqA[0].y - s*stqA[1].x);
        float2 n1 = make_float2(c*stqA[1].x + s*stqA[0].y, c*stqA[1].y - s*stqA[0].x);
        float2 n2 = make_float2(c*stqA[2].x + s*stqA[3].y, c*stqA[2].y - s*stqA[3].x);
        float2 n3 = make_float2(c*stqA[3].x + s*stqA[2].y, c*stqA[3].y - s*stqA[2].x);
        stqA[0]=n0; stqA[1]=n1; stqA[2]=n2; stqA[3]=n3;
        c = hcB[3]; s = hsB[3];
        n0 = make_float2(c*stqB[0].x + s*stqB[1].y, c*stqB[0].y - s*stqB[1].x);
        n1 = make_float2(c*stqB[1].x + s*stqB[0].y, c*stqB[1].y - s*stqB[0].x);
        n2 = make_float2(c*stqB[2].x + s*stqB[3].y, c*stqB[2].y - s*stqB[3].x);
        n3 = make_float2(c*stqB[3].x + s*stqB[2].y, c*stqB[3].y - s*stqB[2].x);
        stqB[0]=n0; stqB[1]=n1; stqB[2]=n2; stqB[3]=n3;
    }

    // ---- scores: scatter-reduce; lane l computes only rz_l, then broadcast ----
    float rzA[4], rzB[4];
    {
        float n0 = stqA[0].x*stqA[0].x + stqA[0].y*stqA[0].y;
        float n1 = stqA[1].x*stqA[1].x + stqA[1].y*stqA[1].y;
        float n2 = stqA[2].x*stqA[2].x + stqA[2].y*stqA[2].y;
        float n3 = stqA[3].x*stqA[3].x + stqA[3].y*stqA[3].y;
        float nsum = n0 + n1 + n2 + n3;
        float z0A = (l & 2) ? -nsum : nsum;
        float z1A = (l & 1) ? -nsum : nsum;
        float z2A = n0 + n1 - n2 - n3;
        float z3A = n0 - n1 + n2 - n3;

        n0 = stqB[0].x*stqB[0].x + stqB[0].y*stqB[0].y;
        n1 = stqB[1].x*stqB[1].x + stqB[1].y*stqB[1].y;
        n2 = stqB[2].x*stqB[2].x + stqB[2].y*stqB[2].y;
        n3 = stqB[3].x*stqB[3].x + stqB[3].y*stqB[3].y;
        nsum = n0 + n1 + n2 + n3;
        float z0B = (l & 2) ? -nsum : nsum;
        float z1B = (l & 1) ? -nsum : nsum;
        float z2B = n0 + n1 - n2 - n3;
        float z3B = n0 - n1 + n2 - n3;

        float x0A = 0.f, x1A = 0.f, x0B = 0.f, x1B = 0.f;
        #pragma unroll
        for (int r = 0; r < 4; r++){
            float2 oA = shflx(stqA[r], 2);
            float2 oB = shflx(stqB[r], 2);
            x0A += stqA[r].x*oA.x + stqA[r].y*oA.y;
            x0B += stqB[r].x*oB.x + stqB[r].y*oB.y;
        }
        #pragma unroll
        for (int r = 0; r < 4; r++){
            float2 oA = shflx(stqA[r], 1);
            float2 oB = shflx(stqB[r], 1);
            x1A += stqA[r].x*oA.x + stqA[r].y*oA.y;
            x1B += stqB[r].x*oB.x + stqB[r].y*oB.y;
        }
        float x2A = 2.f*(stqA[0].x*stqA[2].x + stqA[0].y*stqA[2].y + stqA[1].x*stqA[3].x + stqA[1].y*stqA[3].y);
        float x3A = 2.f*(stqA[0].x*stqA[1].x + stqA[0].y*stqA[1].y + stqA[2].x*stqA[3].x + stqA[2].y*stqA[3].y);
        float x2B = 2.f*(stqB[0].x*stqB[2].x + stqB[0].y*stqB[2].y + stqB[1].x*stqB[3].x + stqB[1].y*stqB[3].y);
        float x3B = 2.f*(stqB[0].x*stqB[1].x + stqB[0].y*stqB[1].y + stqB[2].x*stqB[3].x + stqB[2].y*stqB[3].y);

        float zlA = scat4(z0A, z1A, z2A, z3A, l);
        float xlA = scat4(x0A, x1A, x2A, x3A, l) * sKx[l];
        float zlB = scat4(z0B, z1B, z2B, z3B, l);
        float xlB = scat4(x0B, x1B, x2B, x3B, l) * sKx[l];

        float rzlA = fast_tanh(sqrtf(zlA*zlA + xlA*xlA)) * (0.5f * PI_F);
        float rzlB = fast_tanh(sqrtf(zlB*zlB + xlB*xlB)) * (0.5f * PI_F);
        #pragma unroll
        for (int w = 0; w < 4; w++){
            rzA[w] = __shfl_sync(0xffffffffu, rzlA, w, 4);
            rzB[w] = __shfl_sync(0xffffffffu, rzlB, w, 4);
        }
    }

    // ---- v path: RZ phases ----
    {
        float phlA = ((l & 2) ? rzA[0] : -rzA[0]) + ((l & 1) ? rzA[1] : -rzA[1]);
        float phlB = ((l & 2) ? rzB[0] : -rzB[0]) + ((l & 1) ? rzB[1] : -rzB[1]);
        #pragma unroll
        for (int r = 0; r < 4; r++){
            float phA = phlA + ((r & 2) ? rzA[2] : -rzA[2]) + ((r & 1) ? rzA[3] : -rzA[3]);
            float phB = phlB + ((r & 2) ? rzB[2] : -rzB[2]) + ((r & 1) ? rzB[3] : -rzB[3]);
            float spA, cpA, spB, cpB;
            __sincosf(phA, &spA, &cpA);
            __sincosf(phB, &spB, &cpB);
            stvA[r] = make_float2(stvA[r].x*cpA - stvA[r].y*spA, stvA[r].x*spA + stvA[r].y*cpA);
            stvB[r] = make_float2(stvB[r].x*cpB - stvB[r].y*spB, stvB[r].x*spB + stvB[r].y*cpB);
        }
    }
    // CNOT(0,1): lanes with (l&2) take partner (l^1)'s value
    #pragma unroll
    for (int r = 0; r < 4; r++){
        float2 oA = shflx(stvA[r], 1);
        float2 oB = shflx(stvB[r], 1);
        if (l & 2){ stvA[r] = oA; stvB[r] = oB; }
    }
    // CNOT(1,2): if (l&1): swap rows r <-> r^2
    if (l & 1){
        float2 tq = stvA[0]; stvA[0] = stvA[2]; stvA[2] = tq;
        tq = stvA[1]; stvA[1] = stvA[3]; stvA[3] = tq;
        tq = stvB[0]; stvB[0] = stvB[2]; stvB[2] = tq;
        tq = stvB[1]; stvB[1] = stvB[3]; stvB[3] = tq;
    }
    // CNOT(2,3): swap rows 2,3
    { float2 tq = stvA[2]; stvA[2] = stvA[3]; stvA[3] = tq;
      tq = stvB[2]; stvB[2] = stvB[3]; stvB[3] = tq; }

    // ---- final expectations: scatter-reduce straight to owning lane ----
    float e0A, e1A, e0B, e1B;
    {
        float n0 = stvA[0].x*stvA[0].x + stvA[0].y*stvA[0].y;
        float n1 = stvA[1].x*stvA[1].x + stvA[1].y*stvA[1].y;
        float n2 = stvA[2].x*stvA[2].x + stvA[2].y*stvA[2].y;
        float n3 = stvA[3].x*stvA[3].x + stvA[3].y*stvA[3].y;
        float qs = n0 + n1 + n2 + n3;
        float o0A = (l & 2) ? -qs : qs;
        float o1A = (l & 1) ? -qs : qs;
        float o2A = n0 + n1 - n2 - n3;
        float o3A = n0 - n1 + n2 - n3;

        n0 = stvB[0].x*stvB[0].x + stvB[0].y*stvB[0].y;
        n1 = stvB[1].x*stvB[1].x + stvB[1].y*stvB[1].y;
        n2 = stvB[2].x*stvB[2].x + stvB[2].y*stvB[2].y;
        n3 = stvB[3].x*stvB[3].x + stvB[3].y*stvB[3].y;
        qs = n0 + n1 + n2 + n3;
        float o0B = (l & 2) ? -qs : qs;
        float o1B = (l & 1) ? -qs : qs;
        float o2B = n0 + n1 - n2 - n3;
        float o3B = n0 - n1 + n2 - n3;

        float o4A = 0.f, o5A = 0.f, o4B = 0.f, o5B = 0.f;
        #pragma unroll
        for (int r = 0; r < 4; r++){
            float2 oA = shflx(stvA[r], 2);
            float2 oB = shflx(stvB[r], 2);
            o4A += stvA[r].x*oA.x + stvA[r].y*oA.y;
            o4B += stvB[r].x*oB.x + stvB[r].y*oB.y;
        }
        #pragma unroll
        for (int r = 0; r < 4; r++){
            float2 oA = shflx(stvA[r], 1);
            float2 oB = shflx(stvB[r], 1);
            o5A += stvA[r].x*oA.x + stvA[r].y*oA.y;
            o5B += stvB[r].x*oB.x + stvB[r].y*oB.y;
        }
        float o6A = 2.f*(stvA[0].x*stvA[2].x + stvA[0].y*stvA[2].y + stvA[1].x*stvA[3].x + stvA[1].y*stvA[3].y);
        float o7A = 2.f*(stvA[0].x*stvA[1].x + stvA[0].y*stvA[1].y + stvA[2].x*stvA[3].x + stvA[2].y*stvA[3].y);
        float o6B = 2.f*(stvB[0].x*stvB[2].x + stvB[0].y*stvB[2].y + stvB[1].x*stvB[3].x + stvB[1].y*stvB[3].y);
        float o7B = 2.f*(stvB[0].x*stvB[1].x + stvB[0].y*stvB[1].y + stvB[2].x*stvB[3].x + stvB[2].y*stvB[3].y);

        e0A = scat4(o0A, o2A, o4A, o6A, l);   // channel 2l
        e1A = scat4(o1A, o3A, o5A, o7A, l);   // channel 2l+1
        e0B = scat4(o0B, o2B, o4B, o6B, l);
        e1B = scat4(o1B, o3B, o5B, o7B, l);
    }

    // ---- distributed LN / GELU / head: lane l handles channels 2l, 2l+1 ----
    {
        int c0 = 2*l, c1 = 2*l + 1;

        float mpA = e0A + e1A, mpB = e0B + e1B;
        mpA += __shfl_xor_sync(0xffffffffu, mpA, 1);
        mpB += __shfl_xor_sync(0xffffffffu, mpB, 1);
        mpA += __shfl_xor_sync(0xffffffffu, mpA, 2);
        mpB += __shfl_xor_sync(0xffffffffu, mpB, 2);
        float muA = mpA * 0.125f, muB = mpB * 0.125f;

        float d0A = e0A - muA, d1A = e1A - muA;
        float d0B = e0B - muB, d1B = e1B - muB;
        float vpA = d0A*d0A + d1A*d1A;
        float vpB = d0B*d0B + d1B*d1B;
        vpA += __shfl_xor_sync(0xffffffffu, vpA, 1);
        vpB += __shfl_xor_sync(0xffffffffu, vpB, 1);
        vpA += __shfl_xor_sync(0xffffffffu, vpA, 2);
        vpB += __shfl_xor_sync(0xffffffffu, vpB, 2);
        float invA = rsqrtf(vpA * 0.125f + 1e-5f);
        float invB = rsqrtf(vpB * 0.125f + 1e-5f);

        float w0 = sLnW[c0], w1 = sLnW[c1], bb0 = sLnB[c0], bb1 = sLnB[c1];
        float y0A = d0A*invA*w0 + bb0, y1A = d1A*invA*w1 + bb1;
        float y0B = d0B*invB*w0 + bb0, y1B = d1B*invB*w1 + bb1;

        const float RS2 = 0.70710678118654752f;
        float g0A = 0.5f*y0A*(1.f + erff(y0A*RS2));
        float g1A = 0.5f*y1A*(1.f + erff(y1A*RS2));
        float g0B = 0.5f*y0B*(1.f + erff(y0B*RS2));
        float g1B = 0.5f*y1B*(1.f + erff(y1B*RS2));

        float hw00 = sHW[c0], hw01 = sHW[c1], hw10 = sHW[8+c0], hw11 = sHW[8+c1];
        float r0A = g0A*hw00 + g1A*hw01;
        float r1A = g0A*hw10 + g1A*hw11;
        float r0B = g0B*hw00 + g1B*hw01;
        float r1B = g0B*hw10 + g1B*hw11;
        r0A += __shfl_xor_sync(0xffffffffu, r0A, 1);
        r1A += __shfl_xor_sync(0xffffffffu, r1A, 1);
        r0B += __shfl_xor_sync(0xffffffffu, r0B, 1);
        r1B += __shfl_xor_sync(0xffffffffu, r1B, 1);
        r0A += __shfl_xor_sync(0xffffffffu, r0A, 2);
        r1A += __shfl_xor_sync(0xffffffffu, r1A, 2);
        r0B += __shfl_xor_sync(0xffffffffu, r0B, 2);
        r1B += __shfl_xor_sync(0xffffffffu, r1B, 2);

        if (l == 0){
            if (okA) ((float2*)out)[sA] = make_float2(r0A + sHB[0], r1A + sHB[1]);
            if (okB) ((float2*)out)[sB] = make_float2(r0B + sHB[0], r1B + sHB[1]);
        }
    }
}

extern "C" void kernel_launch(void* const* d_in, const int* in_sizes, int n_in,
                              void* d_out, int out_size)
{
    const float* x1     = (const float*)d_in[0];
    const float* pre_w  = (const float*)d_in[1];
    const float* pre_b  = (const float*)d_in[2];
    const float* q_rot  = (const float*)d_in[3];
    const float* k_rot  = (const float*)d_in[4];
    const float* v_rot  = (const float*)d_in[5];
    const float* q_crx  = (const float*)d_in[6];
    const float* k_crx  = (const float*)d_in[7];
    const float* v_crx  = (const float*)d_in[8];
    const float* ln_w   = (const float*)d_in[9];
    const float* ln_b   = (const float*)d_in[10];
    const float* head_w = (const float*)d_in[11];
    const float* head_b = (const float*)d_in[12];

    int B = in_sizes[0] / 96;

    setup_kernel<<<17, 32>>>(q_rot, k_rot, v_rot, q_crx, k_crx, v_crx);

    // PDL launch: qc's prologue overlaps setup_kernel; griddepcontrol.wait
    // inside qc orders the g_U* reads after setup completion.
    cudaLaunchConfig_t cfg = {};
    cfg.gridDim  = dim3((unsigned)((B + 31) / 32), 1, 1);
    cfg.blockDim = dim3(64, 1, 1);
    cfg.dynamicSmemBytes = 0;
    cfg.stream = 0;
    cudaLaunchAttribute attrs[1];
    attrs[0].id = cudaLaunchAttributeProgrammaticStreamSerialization;
    attrs[0].val.programmaticStreamSerializationAllowed = 1;
    cfg.attrs = attrs;
    cfg.numAttrs = 1;
    cudaLaunchKernelEx(&cfg, qc_kernel, x1, pre_w, pre_b, ln_w, ln_b,
                       head_w, head_b, (float*)d_out, B);
}

// round 14
// speedup vs baseline: 1.0200x; 1.0175x over previous
#include <cuda_runtime.h>
#include <math.h>

#define PI_F 3.14159265358979323846f

// Precomputed circuit data (setup_kernel -> qc_kernel)
// Odd-parity columns pre-rotated by (-i) so the matvec is a uniform f32x2 FMA.
__device__ float2 g_Uq[16][16];   // [col j][row i]
__device__ float2 g_Uv[16][16];
__device__ float  g_kx[4];        // <X_w> of the fixed k-register state

// ---------- helpers ----------
__device__ __forceinline__ float2 cmul(float2 a, float2 b){
    return make_float2(a.x*b.x - a.y*b.y, a.x*b.y + a.y*b.x);
}
__device__ __forceinline__ float2 cadd(float2 a, float2 b){ return make_float2(a.x+b.x, a.y+b.y); }
__device__ __forceinline__ float2 expi(float a){ float s,c; __sincosf(a,&s,&c); return make_float2(c,s); }
__device__ __forceinline__ float2 cscale(float2 a, float s){ return make_float2(a.x*s, a.y*s); }
__device__ __forceinline__ float2 shflx(float2 v, int m){
    return make_float2(__shfl_xor_sync(0xffffffffu, v.x, m),
                       __shfl_xor_sync(0xffffffffu, v.y, m));
}
__device__ __forceinline__ float fast_tanh(float x){
    float e = __expf(2.f * x);
    return 1.f - 2.f / (e + 1.f);
}
__device__ __forceinline__ unsigned long long pk2(float x, float y){
    unsigned long long r; asm("mov.b64 %0, {%1,%2};" : "=l"(r) : "f"(x), "f"(y)); return r;
}
__device__ __forceinline__ float2 upk2(unsigned long long a){
    float2 r; asm("mov.b64 {%0,%1}, %2;" : "=f"(r.x), "=f"(r.y) : "l"(a)); return r;
}
__device__ __forceinline__ unsigned long long fma2(unsigned long long a, unsigned long long b,
                                                   unsigned long long c){
    unsigned long long d;
    asm("fma.rn.f32x2 %0, %1, %2, %3;" : "=l"(d) : "l"(a), "l"(b), "l"(c));
    return d;
}

// Scatter-reduce 4 quad-lane partials: lane l receives the full sum of var l.
__device__ __forceinline__ float scat4(float v0, float v1, float v2, float v3, int l){
    float t0 = __shfl_xor_sync(0xffffffffu, v0, 2);
    float t1 = __shfl_xor_sync(0xffffffffu, v1, 2);
    float t2 = __shfl_xor_sync(0xffffffffu, v2, 2);
    float t3 = __shfl_xor_sync(0xffffffffu, v3, 2);
    float q0, q1;
    if (l & 2){ q0 = v2 + t2; q1 = v3 + t3; }
    else      { q0 = v0 + t0; q1 = v1 + t1; }
    q0 += __shfl_xor_sync(0xffffffffu, q0, 1);
    q1 += __shfl_xor_sync(0xffffffffu, q1, 1);
    return (l & 1) ? q1 : q0;
}

// fully-unrolled 8-gate initQKV circuit on 16 amplitudes across a 16-lane group
__device__ __forceinline__ float2 sim16(const float* __restrict__ rot,
                                        const float* __restrict__ crx,
                                        int col, int lane)
{
    float2 s = (lane == col) ? make_float2(1.f, 0.f) : make_float2(0.f, 0.f);
    #pragma unroll
    for (int g = 0; g < 8; g++){
        const int pa_[8] = {0,1,2,3,0,1,2,3};
        const int pb_[8] = {1,2,3,0,3,0,1,2};
        const int ma = 8 >> pa_[g], mb = 8 >> pb_[g];

        float phi = rot[3*g], th = rot[3*g+1], om = rot[3*g+2];
        float c, sn; __sincosf(0.5f*th, &sn, &c);
        float2 u00 = cscale(expi(-0.5f*(phi+om)),  c);
        float2 u01 = cscale(expi( 0.5f*(phi-om)), -sn);
        float2 u10 = cscale(expi(-0.5f*(phi-om)),  sn);
        float2 u11 = cscale(expi( 0.5f*(phi+om)),  c);
        float2 o = shflx(s, ma);
        s = (lane & ma) ? cadd(cmul(u10, o), cmul(u11, s))
                        : cadd(cmul(u00, s), cmul(u01, o));

        float cc, ss; __sincosf(0.5f*crx[g], &ss, &cc);
        o = shflx(s, mb);
        if (lane & ma) s = make_float2(cc*s.x + ss*o.y, cc*s.y - ss*o.x);

        o = shflx(s, mb);
        if (lane & ma) s = o;
    }
    return s;
}

// 17 blocks x 32 threads: block b handles chains 2b, 2b+1.
__global__ void __launch_bounds__(32)
setup_kernel(const float* __restrict__ qr, const float* __restrict__ kr,
             const float* __restrict__ vr, const float* __restrict__ qc,
             const float* __restrict__ kc, const float* __restrict__ vc)
{
    int grp  = blockIdx.x * 2 + (threadIdx.x >> 4);   // 0..33
    int lane = threadIdx.x & 15;

    const float* rot; const float* crx; int col;
    if (grp < 16)      { rot = qr; crx = qc; col = grp;      }
    else if (grp < 32) { rot = vr; crx = vc; col = grp - 16; }
    else               { rot = kr; crx = kc; col = 0;        }

    float2 s = sim16(rot, crx, col, lane);

    if (grp < 32){
        if (__popc(col) & 1) s = make_float2(s.y, -s.x);   // pre-rotate by (-i)
        if (grp < 16) g_Uq[col][lane] = s;
        else          g_Uv[col][lane] = s;
    } else {
        #pragma unroll
        for (int w = 0; w < 4; w++){
            int m = 8 >> w;
            float2 o = shflx(s, m);
            float v = s.x*o.x + s.y*o.y;
            v += __shfl_xor_sync(0xffffffffu, v, 1);
            v += __shfl_xor_sync(0xffffffffu, v, 2);
            v += __shfl_xor_sync(0xffffffffu, v, 4);
            v += __shfl_xor_sync(0xffffffffu, v, 8);
            if (grp == 32 && lane == 0) g_kx[w] = v;
        }
    }
}

// 128 threads = 32 quads; ONE sample per quad (no ILP-2: max warps, min span).
// grid = B/32 = 512 -> 2048 warps, ~3.5/SMSP.
// Launched with PDL: prologue up to griddepcontrol.wait overlaps setup_kernel.
__global__ void __launch_bounds__(128, 4)
qc_kernel(const float* __restrict__ x1, const float* __restrict__ pre_w,
          const float* __restrict__ pre_b,
          const float* __restrict__ ln_w, const float* __restrict__ ln_b,
          const float* __restrict__ head_w, const float* __restrict__ head_b,
          float* __restrict__ out, int B)
{
    __shared__ float4 sUq[128];   // 16x16 complex
    __shared__ float4 sUv[128];
    __shared__ float  sW[384];    // pre_w [4][96]
    __shared__ float  sKx[4];
    __shared__ float  sPB[4];
    __shared__ float  sLnW[8], sLnB[8], sHW[16], sHB[2];

    int t = threadIdx.x;

    // ---- phase 1: stage params that do NOT depend on setup_kernel ----
    for (int i = t; i < 384; i += 128) sW[i] = pre_w[i];
    if (t < 4)              sPB[t]     = pre_b[t];
    if (t >= 4 && t < 12)   sLnW[t-4]  = ln_w[t-4];
    if (t >= 12 && t < 20)  sLnB[t-12] = ln_b[t-12];
    if (t >= 20 && t < 36)  sHW[t-20]  = head_w[t-20];
    if (t >= 36 && t < 38)  sHB[t-36]  = head_b[t-36];
    __syncthreads();

    int q = t >> 2;                      // quad id 0..31
    int l = t & 3;                       // quad lane: rows 4l..4l+3
    int s_idx = blockIdx.x * 32 + q;
    bool ok = s_idx < B;
    int sl = ok ? s_idx : 0;

    const float4* sW4 = (const float4*)sW;

    // ---- x = x1[s] @ pre_w.T + pre_b (setup-independent) ----
    float a0 = 0.f, a1 = 0.f, a2 = 0.f, a3 = 0.f;
    {
        const float4* row = (const float4*)(x1 + (size_t)sl * 96) + l * 6;
        #pragma unroll
        for (int k = 0; k < 6; k++){
            float4 v = row[k];
            float4 w0 = sW4[      l*6 + k];
            float4 w1 = sW4[ 24 + l*6 + k];
            float4 w2 = sW4[ 48 + l*6 + k];
            float4 w3 = sW4[ 72 + l*6 + k];
            a0 += v.x*w0.x + v.y*w0.y + v.z*w0.z + v.w*w0.w;
            a1 += v.x*w1.x + v.y*w1.y + v.z*w1.z + v.w*w1.w;
            a2 += v.x*w2.x + v.y*w2.y + v.z*w2.z + v.w*w2.w;
            a3 += v.x*w3.x + v.y*w3.y + v.z*w3.z + v.w*w3.w;
        }
        #pragma unroll
        for (int d = 1; d <= 2; d <<= 1){
            a0 += __shfl_xor_sync(0xffffffffu, a0, d);
            a1 += __shfl_xor_sync(0xffffffffu, a1, d);
            a2 += __shfl_xor_sync(0xffffffffu, a2, d);
            a3 += __shfl_xor_sync(0xffffffffu, a3, d);
        }
    }

    float hc[4], hs[4];
    {
        float xw[4] = { a0 + sPB[0], a1 + sPB[1], a2 + sPB[2], a3 + sPB[3] };
        #pragma unroll
        for (int w = 0; w < 4; w++) __sincosf(0.5f * xw[w], &hs[w], &hc[w]);
    }

    // product-state magnitudes ((-1) of (-i)^popc folded in; (-i) itself is in U)
    float m[16];
    #pragma unroll
    for (int i = 0; i < 16; i++){
        float v = ((i&8)?hs[0]:hc[0]) * ((i&4)?hs[1]:hc[1]) * ((i&2)?hs[2]:hc[2]) * ((i&1)?hs[3]:hc[3]);
        m[i] = (__popc(i) & 2) ? -v : v;
    }

    // ---- phase 2: wait for setup_kernel's results, then stage them ----
    asm volatile("griddepcontrol.wait;" ::: "memory");
    sUq[t] = ((const float4*)g_Uq)[t];
    sUv[t] = ((const float4*)g_Uv)[t];
    if (t < 4) sKx[t] = g_kx[t];
    __syncthreads();

    const ulonglong2* Uq64 = (const ulonglong2*)sUq;
    const ulonglong2* Uv64 = (const ulonglong2*)sUv;

    // ---- matvecs (rows 4l..4l+3), packed f32x2 FMA ----
    unsigned long long pq[4], pv[4];
    #pragma unroll
    for (int r = 0; r < 4; r++){ pq[r]=0ull; pv[r]=0ull; }
    #pragma unroll
    for (int j = 0; j < 16; j++){
        unsigned long long mj = pk2(m[j], m[j]);
        ulonglong2 qa = Uq64[j*8 + 2*l];
        ulonglong2 qb = Uq64[j*8 + 2*l + 1];
        ulonglong2 va = Uv64[j*8 + 2*l];
        ulonglong2 vb = Uv64[j*8 + 2*l + 1];
        pq[0] = fma2(qa.x, mj, pq[0]);
        pq[1] = fma2(qa.y, mj, pq[1]);
        pq[2] = fma2(qb.x, mj, pq[2]);
        pq[3] = fma2(qb.y, mj, pq[3]);
        pv[0] = fma2(va.x, mj, pv[0]);
        pv[1] = fma2(va.y, mj, pv[1]);
        pv[2] = fma2(vb.x, mj, pv[2]);
        pv[3] = fma2(vb.y, mj, pv[3]);
    }
    float2 stq[4], stv[4];
    #pragma unroll
    for (int r = 0; r < 4; r++){ stq[r] = upk2(pq[r]); stv[r] = upk2(pv[r]); }

    // ---- q path: RX(x) layer (symmetric pair update) ----
    #pragma unroll
    for (int w = 0; w < 2; w++){
        int d = 2 >> w;   // wire0: lane^2, wire1: lane^1
        float c = hc[w], s = hs[w];
        #pragma unroll
        for (int r = 0; r < 4; r++){
            float2 o = shflx(stq[r], d);
            stq[r] = make_float2(c*stq[r].x + s*o.y, c*stq[r].y - s*o.x);
        }
    }
    {   // wire2 (bit1): rows r <-> r^2
        float c = hc[2], s = hs[2];
        float2 n0 = make_float2(c*stq[0].x + s*stq[2].y, c*stq[0].y - s*stq[2].x);
        float2 n2 = make_float2(c*stq[2].x + s*stq[0].y, c*stq[2].y - s*stq[0].x);
        float2 n1 = make_float2(c*stq[1].x + s*stq[3].y, c*stq[1].y - s*stq[3].x);
        float2 n3 = make_float2(c*stq[3].x + s*stq[1].y, c*stq[3].y - s*stq[1].x);
        stq[0]=n0; stq[1]=n1; stq[2]=n2; stq[3]=n3;
    }
    {   // wire3 (bit0): rows r <-> r^1
        float c = hc[3], s = hs[3];
        float2 n0 = make_float2(c*stq[0].x + s*stq[1].y, c*stq[0].y - s*stq[1].x);
        float2 n1 = make_float2(c*stq[1].x + s*stq[0].y, c*stq[1].y - s*stq[0].x);
        float2 n2 = make_float2(c*stq[2].x + s*stq[3].y, c*stq[2].y - s*stq[3].x);
        float2 n3 = make_float2(c*stq[3].x + s*stq[2].y, c*stq[3].y - s*stq[2].x);
        stq[0]=n0; stq[1]=n1; stq[2]=n2; stq[3]=n3;
    }

    // ---- scores: scatter-reduce; lane l computes only rz_l, then broadcast ----
    float rz[4];
    {
        float n0 = stq[0].x*stq[0].x + stq[0].y*stq[0].y;
        float n1 = stq[1].x*stq[1].x + stq[1].y*stq[1].y;
        float n2 = stq[2].x*stq[2].x + stq[2].y*stq[2].y;
        float n3 = stq[3].x*stq[3].x + stq[3].y*stq[3].y;
        float nsum = n0 + n1 + n2 + n3;
        float z0 = (l & 2) ? -nsum : nsum;
        float z1 = (l & 1) ? -nsum : nsum;
        float z2 = n0 + n1 - n2 - n3;
        float z3 = n0 - n1 + n2 - n3;

        float x0 = 0.f, x1m = 0.f;
        #pragma unroll
        for (int r = 0; r < 4; r++){
            float2 o = shflx(stq[r], 2);
            x0 += stq[r].x*o.x + stq[r].y*o.y;
        }
        #pragma unroll
        for (int r = 0; r < 4; r++){
            float2 o = shflx(stq[r], 1);
            x1m += stq[r].x*o.x + stq[r].y*o.y;
        }
        float x2 = 2.f*(stq[0].x*stq[2].x + stq[0].y*stq[2].y + stq[1].x*stq[3].x + stq[1].y*stq[3].y);
        float x3 = 2.f*(stq[0].x*stq[1].x + stq[0].y*stq[1].y + stq[2].x*stq[3].x + stq[2].y*stq[3].y);

        float zl = scat4(z0, z1, z2, z3, l);
        float xl = scat4(x0, x1m, x2, x3, l) * sKx[l];

        float rzl = fast_tanh(sqrtf(zl*zl + xl*xl)) * (0.5f * PI_F);
        #pragma unroll
        for (int w = 0; w < 4; w++)
            rz[w] = __shfl_sync(0xffffffffu, rzl, w, 4);
    }

    // ---- v path: RZ phases ----
    {
        float phl = ((l & 2) ? rz[0] : -rz[0]) + ((l & 1) ? rz[1] : -rz[1]);
        #pragma unroll
        for (int r = 0; r < 4; r++){
            float ph = phl + ((r & 2) ? rz[2] : -rz[2]) + ((r & 1) ? rz[3] : -rz[3]);
            float sp, cp; __sincosf(ph, &sp, &cp);
            stv[r] = make_float2(stv[r].x*cp - stv[r].y*sp, stv[r].x*sp + stv[r].y*cp);
        }
    }
    // CNOT(0,1): lanes with (l&2) take partner (l^1)'s value
    #pragma unroll
    for (int r = 0; r < 4; r++){
        float2 o = shflx(stv[r], 1);
        if (l & 2) stv[r] = o;
    }
    // CNOT(1,2): if (l&1): swap rows r <-> r^2
    if (l & 1){
        float2 tq = stv[0]; stv[0] = stv[2]; stv[2] = tq;
        tq = stv[1]; stv[1] = stv[3]; stv[3] = tq;
    }
    // CNOT(2,3): swap rows 2,3
    { float2 tq = stv[2]; stv[2] = stv[3]; stv[3] = tq; }

    // ---- final expectations: scatter-reduce straight to owning lane ----
    float e0, e1;
    {
        float n0 = stv[0].x*stv[0].x + stv[0].y*stv[0].y;
        float n1 = stv[1].x*stv[1].x + stv[1].y*stv[1].y;
        float n2 = stv[2].x*stv[2].x + stv[2].y*stv[2].y;
        float n3 = stv[3].x*stv[3].x + stv[3].y*stv[3].y;
        float qs = n0 + n1 + n2 + n3;
        float o0 = (l & 2) ? -qs : qs;
        float o1 = (l & 1) ? -qs : qs;
        float o2 = n0 + n1 - n2 - n3;
        float o3 = n0 - n1 + n2 - n3;

        float o4 = 0.f, o5 = 0.f;
        #pragma unroll
        for (int r = 0; r < 4; r++){
            float2 o = shflx(stv[r], 2);
            o4 += stv[r].x*o.x + stv[r].y*o.y;
        }
        #pragma unroll
        for (int r = 0; r < 4; r++){
            float2 o = shflx(stv[r], 1);
            o5 += stv[r].x*o.x + stv[r].y*o.y;
        }
        float o6 = 2.f*(stv[0].x*stv[2].x + stv[0].y*stv[2].y + stv[1].x*stv[3].x + stv[1].y*stv[3].y);
        float o7 = 2.f*(stv[0].x*stv[1].x + stv[0].y*stv[1].y + stv[2].x*stv[3].x + stv[2].y*stv[3].y);

        e0 = scat4(o0, o2, o4, o6, l);   // channel 2l
        e1 = scat4(o1, o3, o5, o7, l);   // channel 2l+1
    }

    // ---- distributed LN / GELU / head: lane l handles channels 2l, 2l+1 ----
    {
        int c0 = 2*l, c1 = 2*l + 1;

        float mp = e0 + e1;
        mp += __shfl_xor_sync(0xffffffffu, mp, 1);
        mp += __shfl_xor_sync(0xffffffffu, mp, 2);
        float mu = mp * 0.125f;

        float d0 = e0 - mu, d1 = e1 - mu;
        float vp = d0*d0 + d1*d1;
        vp += __shfl_xor_sync(0xffffffffu, vp, 1);
        vp += __shfl_xor_sync(0xffffffffu, vp, 2);
        float inv = rsqrtf(vp * 0.125f + 1e-5f);

        float w0 = sLnW[c0], w1 = sLnW[c1], bb0 = sLnB[c0], bb1 = sLnB[c1];
        float y0 = d0*inv*w0 + bb0, y1 = d1*inv*w1 + bb1;

        const float RS2 = 0.70710678118654752f;
        float g0 = 0.5f*y0*(1.f + erff(y0*RS2));
        float g1 = 0.5f*y1*(1.f + erff(y1*RS2));

        float hw00 = sHW[c0], hw01 = sHW[c1], hw10 = sHW[8+c0], hw11 = sHW[8+c1];
        float r0 = g0*hw00 + g1*hw01;
        float r1 = g0*hw10 + g1*hw11;
        r0 += __shfl_xor_sync(0xffffffffu, r0, 1);
        r1 += __shfl_xor_sync(0xffffffffu, r1, 1);
        r0 += __shfl_xor_sync(0xffffffffu, r0, 2);
        r1 += __shfl_xor_sync(0xffffffffu, r1, 2);

        if (l == 0 && ok)
            ((float2*)out)[s_idx] = make_float2(r0 + sHB[0], r1 + sHB[1]);
    }
}

extern "C" void kernel_launch(void* const* d_in, const int* in_sizes, int n_in,
                              void* d_out, int out_size)
{
    const float* x1     = (const float*)d_in[0];
    const float* pre_w  = (const float*)d_in[1];
    const float* pre_b  = (const float*)d_in[2];
    const float* q_rot  = (const float*)d_in[3];
    const float* k_rot  = (const float*)d_in[4];
    const float* v_rot  = (const float*)d_in[5];
    const float* q_crx  = (const float*)d_in[6];
    const float* k_crx  = (const float*)d_in[7];
    const float* v_crx  = (const float*)d_in[8];
    const float* ln_w   = (const float*)d_in[9];
    const float* ln_b   = (const float*)d_in[10];
    const float* head_w = (const float*)d_in[11];
    const float* head_b = (const float*)d_in[12];

    int B = in_sizes[0] / 96;

    setup_kernel<<<17, 32>>>(q_rot, k_rot, v_rot, q_crx, k_crx, v_crx);

    // PDL launch: qc's prologue overlaps setup_kernel; griddepcontrol.wait
    // inside qc orders the g_U* reads after setup completion.
    cudaLaunchConfig_t cfg = {};
    cfg.gridDim  = dim3((unsigned)((B + 31) / 32), 1, 1);
    cfg.blockDim = dim3(128, 1, 1);
    cfg.dynamicSmemBytes = 0;
    cfg.stream = 0;
    cudaLaunchAttribute attrs[1];
    attrs[0].id = cudaLaunchAttributeProgrammaticStreamSerialization;
    attrs[0].val.programmaticStreamSerializationAllowed = 1;
    cfg.attrs = attrs;
    cfg.numAttrs = 1;
    cudaLaunchKernelEx(&cfg, qc_kernel, x1, pre_w, pre_b, ln_w, ln_b,
                       head_w, head_b, (float*)d_out, B);
}

// round 15
// speedup vs baseline: 1.0226x; 1.0025x over previous
#include <cuda_runtime.h>
#include <math.h>

#define PI_F 3.14159265358979323846f

// Precomputed circuit data (setup_kernel -> qc_kernel)
// Odd-parity columns pre-rotated by (-i) so the matvec is a uniform f32x2 FMA.
__device__ float2 g_Uq[16][16];   // [col j][row i]
__device__ float2 g_Uv[16][16];
__device__ float  g_kx[4];        // <X_w> of the fixed k-register state

// ---------- helpers ----------
__device__ __forceinline__ float2 cmul(float2 a, float2 b){
    return make_float2(a.x*b.x - a.y*b.y, a.x*b.y + a.y*b.x);
}
__device__ __forceinline__ float2 cadd(float2 a, float2 b){ return make_float2(a.x+b.x, a.y+b.y); }
__device__ __forceinline__ float2 expi(float a){ float s,c; __sincosf(a,&s,&c); return make_float2(c,s); }
__device__ __forceinline__ float2 cscale(float2 a, float s){ return make_float2(a.x*s, a.y*s); }
__device__ __forceinline__ float2 shflx(float2 v, int m){
    return make_float2(__shfl_xor_sync(0xffffffffu, v.x, m),
                       __shfl_xor_sync(0xffffffffu, v.y, m));
}
__device__ __forceinline__ float fast_tanh(float x){
    float e = __expf(2.f * x);
    return 1.f - 2.f / (e + 1.f);
}
__device__ __forceinline__ unsigned long long pk2(float x, float y){
    unsigned long long r; asm("mov.b64 %0, {%1,%2};" : "=l"(r) : "f"(x), "f"(y)); return r;
}
__device__ __forceinline__ float2 upk2(unsigned long long a){
    float2 r; asm("mov.b64 {%0,%1}, %2;" : "=f"(r.x), "=f"(r.y) : "l"(a)); return r;
}
__device__ __forceinline__ unsigned long long fma2(unsigned long long a, unsigned long long b,
                                                   unsigned long long c){
    unsigned long long d;
    asm("fma.rn.f32x2 %0, %1, %2, %3;" : "=l"(d) : "l"(a), "l"(b), "l"(c));
    return d;
}

// Scatter-reduce 4 quad-lane partials: lane l receives the full sum of var l.
__device__ __forceinline__ float scat4(float v0, float v1, float v2, float v3, int l){
    float t0 = __shfl_xor_sync(0xffffffffu, v0, 2);
    float t1 = __shfl_xor_sync(0xffffffffu, v1, 2);
    float t2 = __shfl_xor_sync(0xffffffffu, v2, 2);
    float t3 = __shfl_xor_sync(0xffffffffu, v3, 2);
    float q0, q1;
    if (l & 2){ q0 = v2 + t2; q1 = v3 + t3; }
    else      { q0 = v0 + t0; q1 = v1 + t1; }
    q0 += __shfl_xor_sync(0xffffffffu, q0, 1);
    q1 += __shfl_xor_sync(0xffffffffu, q1, 1);
    return (l & 1) ? q1 : q0;
}

// fully-unrolled 8-gate initQKV circuit on 16 amplitudes across a 16-lane group
__device__ __forceinline__ float2 sim16(const float* __restrict__ rot,
                                        const float* __restrict__ crx,
                                        int col, int lane)
{
    float2 s = (lane == col) ? make_float2(1.f, 0.f) : make_float2(0.f, 0.f);
    #pragma unroll
    for (int g = 0; g < 8; g++){
        const int pa_[8] = {0,1,2,3,0,1,2,3};
        const int pb_[8] = {1,2,3,0,3,0,1,2};
        const int ma = 8 >> pa_[g], mb = 8 >> pb_[g];

        float phi = rot[3*g], th = rot[3*g+1], om = rot[3*g+2];
        float c, sn; __sincosf(0.5f*th, &sn, &c);
        float2 u00 = cscale(expi(-0.5f*(phi+om)),  c);
        float2 u01 = cscale(expi( 0.5f*(phi-om)), -sn);
        float2 u10 = cscale(expi(-0.5f*(phi-om)),  sn);
        float2 u11 = cscale(expi( 0.5f*(phi+om)),  c);
        float2 o = shflx(s, ma);
        s = (lane & ma) ? cadd(cmul(u10, o), cmul(u11, s))
                        : cadd(cmul(u00, s), cmul(u01, o));

        float cc, ss; __sincosf(0.5f*crx[g], &ss, &cc);
        o = shflx(s, mb);
        if (lane & ma) s = make_float2(cc*s.x + ss*o.y, cc*s.y - ss*o.x);

        o = shflx(s, mb);
        if (lane & ma) s = o;
    }
    return s;
}

// 17 blocks x 32 threads: block b handles chains 2b, 2b+1.
__global__ void __launch_bounds__(32)
setup_kernel(const float* __restrict__ qr, const float* __restrict__ kr,
             const float* __restrict__ vr, const float* __restrict__ qc,
             const float* __restrict__ kc, const float* __restrict__ vc)
{
    int grp  = blockIdx.x * 2 + (threadIdx.x >> 4);   // 0..33
    int lane = threadIdx.x & 15;

    const float* rot; const float* crx; int col;
    if (grp < 16)      { rot = qr; crx = qc; col = grp;      }
    else if (grp < 32) { rot = vr; crx = vc; col = grp - 16; }
    else               { rot = kr; crx = kc; col = 0;        }

    float2 s = sim16(rot, crx, col, lane);

    if (grp < 32){
        if (__popc(col) & 1) s = make_float2(s.y, -s.x);   // pre-rotate by (-i)
        if (grp < 16) g_Uq[col][lane] = s;
        else          g_Uv[col][lane] = s;
    } else {
        #pragma unroll
        for (int w = 0; w < 4; w++){
            int m = 8 >> w;
            float2 o = shflx(s, m);
            float v = s.x*o.x + s.y*o.y;
            v += __shfl_xor_sync(0xffffffffu, v, 1);
            v += __shfl_xor_sync(0xffffffffu, v, 2);
            v += __shfl_xor_sync(0xffffffffu, v, 4);
            v += __shfl_xor_sync(0xffffffffu, v, 8);
            if (grp == 32 && lane == 0) g_kx[w] = v;
        }
    }
}

// 128 threads = 32 quads; ONE sample per quad. grid = B/32 = 512 -> 2048 warps.
// __launch_bounds__(128, 6): cap regs ~85 so 6 blocks/SM fit -> 24 warps/SM (6/SMSP hiding).
// Launched with PDL: prologue up to griddepcontrol.wait overlaps setup_kernel.
__global__ void __launch_bounds__(128, 6)
qc_kernel(const float* __restrict__ x1, const float* __restrict__ pre_w,
          const float* __restrict__ pre_b,
          const float* __restrict__ ln_w, const float* __restrict__ ln_b,
          const float* __restrict__ head_w, const float* __restrict__ head_b,
          float* __restrict__ out, int B)
{
    __shared__ float4 sUq[128];   // 16x16 complex
    __shared__ float4 sUv[128];
    __shared__ float  sW[384];    // pre_w [4][96]
    __shared__ float  sKx[4];
    __shared__ float  sPB[4];
    __shared__ float  sLnW[8], sLnB[8], sHW[16], sHB[2];

    int t = threadIdx.x;

    // ---- phase 1: stage params that do NOT depend on setup_kernel ----
    for (int i = t; i < 384; i += 128) sW[i] = pre_w[i];
    if (t < 4)              sPB[t]     = pre_b[t];
    if (t >= 4 && t < 12)   sLnW[t-4]  = ln_w[t-4];
    if (t >= 12 && t < 20)  sLnB[t-12] = ln_b[t-12];
    if (t >= 20 && t < 36)  sHW[t-20]  = head_w[t-20];
    if (t >= 36 && t < 38)  sHB[t-36]  = head_b[t-36];
    __syncthreads();

    int q = t >> 2;                      // quad id 0..31
    int l = t & 3;                       // quad lane: rows 4l..4l+3
    int s_idx = blockIdx.x * 32 + q;
    bool ok = s_idx < B;
    int sl = ok ? s_idx : 0;

    const float4* sW4 = (const float4*)sW;

    // ---- x = x1[s] @ pre_w.T + pre_b (setup-independent) ----
    float a0 = 0.f, a1 = 0.f, a2 = 0.f, a3 = 0.f;
    {
        const float4* row = (const float4*)(x1 + (size_t)sl * 96) + l * 6;
        #pragma unroll
        for (int k = 0; k < 6; k++){
            float4 v = row[k];
            float4 w0 = sW4[      l*6 + k];
            float4 w1 = sW4[ 24 + l*6 + k];
            float4 w2 = sW4[ 48 + l*6 + k];
            float4 w3 = sW4[ 72 + l*6 + k];
            a0 += v.x*w0.x + v.y*w0.y + v.z*w0.z + v.w*w0.w;
            a1 += v.x*w1.x + v.y*w1.y + v.z*w1.z + v.w*w1.w;
            a2 += v.x*w2.x + v.y*w2.y + v.z*w2.z + v.w*w2.w;
            a3 += v.x*w3.x + v.y*w3.y + v.z*w3.z + v.w*w3.w;
        }
        #pragma unroll
        for (int d = 1; d <= 2; d <<= 1){
            a0 += __shfl_xor_sync(0xffffffffu, a0, d);
            a1 += __shfl_xor_sync(0xffffffffu, a1, d);
            a2 += __shfl_xor_sync(0xffffffffu, a2, d);
            a3 += __shfl_xor_sync(0xffffffffu, a3, d);
        }
    }

    float hc[4], hs[4];
    {
        float xw[4] = { a0 + sPB[0], a1 + sPB[1], a2 + sPB[2], a3 + sPB[3] };
        #pragma unroll
        for (int w = 0; w < 4; w++) __sincosf(0.5f * xw[w], &hs[w], &hc[w]);
    }

    // product-state magnitudes ((-1) of (-i)^popc folded in; (-i) itself is in U)
    float m[16];
    #pragma unroll
    for (int i = 0; i < 16; i++){
        float v = ((i&8)?hs[0]:hc[0]) * ((i&4)?hs[1]:hc[1]) * ((i&2)?hs[2]:hc[2]) * ((i&1)?hs[3]:hc[3]);
        m[i] = (__popc(i) & 2) ? -v : v;
    }

    // ---- phase 2: wait for setup_kernel's results, then stage them ----
    asm volatile("griddepcontrol.wait;" ::: "memory");
    sUq[t] = ((const float4*)g_Uq)[t];
    sUv[t] = ((const float4*)g_Uv)[t];
    if (t < 4) sKx[t] = g_kx[t];
    __syncthreads();

    const ulonglong2* Uq64 = (const ulonglong2*)sUq;
    const ulonglong2* Uv64 = (const ulonglong2*)sUv;

    // ---- matvecs (rows 4l..4l+3), packed f32x2 FMA ----
    unsigned long long pq[4], pv[4];
    #pragma unroll
    for (int r = 0; r < 4; r++){ pq[r]=0ull; pv[r]=0ull; }
    #pragma unroll
    for (int j = 0; j < 16; j++){
        unsigned long long mj = pk2(m[j], m[j]);
        ulonglong2 qa = Uq64[j*8 + 2*l];
        ulonglong2 qb = Uq64[j*8 + 2*l + 1];
        ulonglong2 va = Uv64[j*8 + 2*l];
        ulonglong2 vb = Uv64[j*8 + 2*l + 1];
        pq[0] = fma2(qa.x, mj, pq[0]);
        pq[1] = fma2(qa.y, mj, pq[1]);
        pq[2] = fma2(qb.x, mj, pq[2]);
        pq[3] = fma2(qb.y, mj, pq[3]);
        pv[0] = fma2(va.x, mj, pv[0]);
        pv[1] = fma2(va.y, mj, pv[1]);
        pv[2] = fma2(vb.x, mj, pv[2]);
        pv[3] = fma2(vb.y, mj, pv[3]);
    }
    float2 stq[4], stv[4];
    #pragma unroll
    for (int r = 0; r < 4; r++){ stq[r] = upk2(pq[r]); stv[r] = upk2(pv[r]); }

    // ---- q path: RX(x) layer (symmetric pair update) ----
    #pragma unroll
    for (int w = 0; w < 2; w++){
        int d = 2 >> w;   // wire0: lane^2, wire1: lane^1
        float c = hc[w], s = hs[w];
        #pragma unroll
        for (int r = 0; r < 4; r++){
            float2 o = shflx(stq[r], d);
            stq[r] = make_float2(c*stq[r].x + s*o.y, c*stq[r].y - s*o.x);
        }
    }
    {   // wire2 (bit1): rows r <-> r^2
        float c = hc[2], s = hs[2];
        float2 n0 = make_float2(c*stq[0].x + s*stq[2].y, c*stq[0].y - s*stq[2].x);
        float2 n2 = make_float2(c*stq[2].x + s*stq[0].y, c*stq[2].y - s*stq[0].x);
        float2 n1 = make_float2(c*stq[1].x + s*stq[3].y, c*stq[1].y - s*stq[3].x);
        float2 n3 = make_float2(c*stq[3].x + s*stq[1].y, c*stq[3].y - s*stq[1].x);
        stq[0]=n0; stq[1]=n1; stq[2]=n2; stq[3]=n3;
    }
    {   // wire3 (bit0): rows r <-> r^1
        float c = hc[3], s = hs[3];
        float2 n0 = make_float2(c*stq[0].x + s*stq[1].y, c*stq[0].y - s*stq[1].x);
        float2 n1 = make_float2(c*stq[1].x + s*stq[0].y, c*stq[1].y - s*stq[0].x);
        float2 n2 = make_float2(c*stq[2].x + s*stq[3].y, c*stq[2].y - s*stq[3].x);
        float2 n3 = make_float2(c*stq[3].x + s*stq[2].y, c*stq[3].y - s*stq[2].x);
        stq[0]=n0; stq[1]=n1; stq[2]=n2; stq[3]=n3;
    }

    // ---- scores: scatter-reduce; lane l computes only rz_l, then broadcast ----
    float rz[4];
    {
        float n0 = stq[0].x*stq[0].x + stq[0].y*stq[0].y;
        float n1 = stq[1].x*stq[1].x + stq[1].y*stq[1].y;
        float n2 = stq[2].x*stq[2].x + stq[2].y*stq[2].y;
        float n3 = stq[3].x*stq[3].x + stq[3].y*stq[3].y;
        float nsum = n0 + n1 + n2 + n3;
        float z0 = (l & 2) ? -nsum : nsum;
        float z1 = (l & 1) ? -nsum : nsum;
        float z2 = n0 + n1 - n2 - n3;
        float z3 = n0 - n1 + n2 - n3;

        float x0 = 0.f, x1m = 0.f;
        #pragma unroll
        for (int r = 0; r < 4; r++){
            float2 o = shflx(stq[r], 2);
            x0 += stq[r].x*o.x + stq[r].y*o.y;
        }
        #pragma unroll
        for (int r = 0; r < 4; r++){
            float2 o = shflx(stq[r], 1);
            x1m += stq[r].x*o.x + stq[r].y*o.y;
        }
        float x2 = 2.f*(stq[0].x*stq[2].x + stq[0].y*stq[2].y + stq[1].x*stq[3].x + stq[1].y*stq[3].y);
        float x3 = 2.f*(stq[0].x*stq[1].x + stq[0].y*stq[1].y + stq[2].x*stq[3].x + stq[2].y*stq[3].y);

        float zl = scat4(z0, z1, z2, z3, l);
        float xl = scat4(x0, x1m, x2, x3, l) * sKx[l];

        float rzl = fast_tanh(sqrtf(zl*zl + xl*xl)) * (0.5f * PI_F);
        #pragma unroll
        for (int w = 0; w < 4; w++)
            rz[w] = __shfl_sync(0xffffffffu, rzl, w, 4);
    }

    // ---- v path: RZ phases ----
    {
        float phl = ((l & 2) ? rz[0] : -rz[0]) + ((l & 1) ? rz[1] : -rz[1]);
        #pragma unroll
        for (int r = 0; r < 4; r++){
            float ph = phl + ((r & 2) ? rz[2] : -rz[2]) + ((r & 1) ? rz[3] : -rz[3]);
            float sp, cp; __sincosf(ph, &sp, &cp);
            stv[r] = make_float2(stv[r].x*cp - stv[r].y*sp, stv[r].x*sp + stv[r].y*cp);
        }
    }
    // CNOT(0,1): lanes with (l&2) take partner (l^1)'s value
    #pragma unroll
    for (int r = 0; r < 4; r++){
        float2 o = shflx(stv[r], 1);
        if (l & 2) stv[r] = o;
    }
    // CNOT(1,2): if (l&1): swap rows r <-> r^2
    if (l & 1){
        float2 tq = stv[0]; stv[0] = stv[2]; stv[2] = tq;
        tq = stv[1]; stv[1] = stv[3]; stv[3] = tq;
    }
    // CNOT(2,3): swap rows 2,3
    { float2 tq = stv[2]; stv[2] = stv[3]; stv[3] = tq; }

    // ---- final expectations: scatter-reduce straight to owning lane ----
    float e0, e1;
    {
        float n0 = stv[0].x*stv[0].x + stv[0].y*stv[0].y;
        float n1 = stv[1].x*stv[1].x + stv[1].y*stv[1].y;
        float n2 = stv[2].x*stv[2].x + stv[2].y*stv[2].y;
        float n3 = stv[3].x*stv[3].x + stv[3].y*stv[3].y;
        float qs = n0 + n1 + n2 + n3;
        float o0 = (l & 2) ? -qs : qs;
        float o1 = (l & 1) ? -qs : qs;
        float o2 = n0 + n1 - n2 - n3;
        float o3 = n0 - n1 + n2 - n3;

        float o4 = 0.f, o5 = 0.f;
        #pragma unroll
        for (int r = 0; r < 4; r++){
            float2 o = shflx(stv[r], 2);
            o4 += stv[r].x*o.x + stv[r].y*o.y;
        }
        #pragma unroll
        for (int r = 0; r < 4; r++){
            float2 o = shflx(stv[r], 1);
            o5 += stv[r].x*o.x + stv[r].y*o.y;
        }
        float o6 = 2.f*(stv[0].x*stv[2].x + stv[0].y*stv[2].y + stv[1].x*stv[3].x + stv[1].y*stv[3].y);
        float o7 = 2.f*(stv[0].x*stv[1].x + stv[0].y*stv[1].y + stv[2].x*stv[3].x + stv[2].y*stv[3].y);

        e0 = scat4(o0, o2, o4, o6, l);   // channel 2l
        e1 = scat4(o1, o3, o5, o7, l);   // channel 2l+1
    }

    // ---- distributed LN / GELU / head: lane l handles channels 2l, 2l+1 ----
    {
        int c0 = 2*l, c1 = 2*l + 1;

        float mp = e0 + e1;
        mp += __shfl_xor_sync(0xffffffffu, mp, 1);
        mp += __shfl_xor_sync(0xffffffffu, mp, 2);
        float mu = mp * 0.125f;

        float d0 = e0 - mu, d1 = e1 - mu;
        float vp = d0*d0 + d1*d1;
        vp += __shfl_xor_sync(0xffffffffu, vp, 1);
        vp += __shfl_xor_sync(0xffffffffu, vp, 2);
        float inv = rsqrtf(vp * 0.125f + 1e-5f);

        float w0 = sLnW[c0], w1 = sLnW[c1], bb0 = sLnB[c0], bb1 = sLnB[c1];
        float y0 = d0*inv*w0 + bb0, y1 = d1*inv*w1 + bb1;

        const float RS2 = 0.70710678118654752f;
        float g0 = 0.5f*y0*(1.f + erff(y0*RS2));
        float g1 = 0.5f*y1*(1.f + erff(y1*RS2));

        float hw00 = sHW[c0], hw01 = sHW[c1], hw10 = sHW[8+c0], hw11 = sHW[8+c1];
        float r0 = g0*hw00 + g1*hw01;
        float r1 = g0*hw10 + g1*hw11;
        r0 += __shfl_xor_sync(0xffffffffu, r0, 1);
        r1 += __shfl_xor_sync(0xffffffffu, r1, 1);
        r0 += __shfl_xor_sync(0xffffffffu, r0, 2);
        r1 += __shfl_xor_sync(0xffffffffu, r1, 2);

        if (l == 0 && ok)
            ((float2*)out)[s_idx] = make_float2(r0 + sHB[0], r1 + sHB[1]);
    }
}

extern "C" void kernel_launch(void* const* d_in, const int* in_sizes, int n_in,
                              void* d_out, int out_size)
{
    const float* x1     = (const float*)d_in[0];
    const float* pre_w  = (const float*)d_in[1];
    const float* pre_b  = (const float*)d_in[2];
    const float* q_rot  = (const float*)d_in[3];
    const float* k_rot  = (const float*)d_in[4];
    const float* v_rot  = (const float*)d_in[5];
    const float* q_crx  = (const float*)d_in[6];
    const float* k_crx  = (const float*)d_in[7];
    const float* v_crx  = (const float*)d_in[8];
    const float* ln_w   = (const float*)d_in[9];
    const float* ln_b   = (const float*)d_in[10];
    const float* head_w = (const float*)d_in[11];
    const float* head_b = (const float*)d_in[12];

    int B = in_sizes[0] / 96;

    setup_kernel<<<17, 32>>>(q_rot, k_rot, v_rot, q_crx, k_crx, v_crx);

    // PDL launch: qc's prologue overlaps setup_kernel; griddepcontrol.wait
    // inside qc orders the g_U* reads after setup completion.
    cudaLaunchConfig_t cfg = {};
    cfg.gridDim  = dim3((unsigned)((B + 31) / 32), 1, 1);
    cfg.blockDim = dim3(128, 1, 1);
    cfg.dynamicSmemBytes = 0;
    cfg.stream = 0;
    cudaLaunchAttribute attrs[1];
    attrs[0].id = cudaLaunchAttributeProgrammaticStreamSerialization;
    attrs[0].val.programmaticStreamSerializationAllowed = 1;
    cfg.attrs = attrs;
    cfg.numAttrs = 1;
    cudaLaunchKernelEx(&cfg, qc_kernel, x1, pre_w, pre_b, ln_w, ln_b,
                       head_w, head_b, (float*)d_out, B);
}